// round 7
// baseline (speedup 1.0000x reference)
#include <cuda_runtime.h>
#include <cuda_fp16.h>
#include <cstdint>
#include <math.h>

#define BB 128
#define TT 1024
#define HH 512
#define NCTA 122
#define NTHR 512
#define GT   (NCTA * NTHR)

// smem layout (bytes)
#define PAIR_STRIDE 4608            // 2 bufs x 2304 (16 rows x 144B)
#define OFF_A 0                     // 8 pairs -> 36864
#define OFF_W 36864                 // persistent weights (max 133120)
#define SMEM_BYTES 169984

// ------------------------- persistent device state ---------------------------
__device__ float g_ig0[65 * 1536];
__device__ float g_h_f32[3][2][BB][HH];
__device__ __align__(16) __half g_hA[3][2][BB * HH];        // fp16 h slabs [lay][pp][b*512+g]
__device__ __align__(16) __half g_wf16[6][2][1536 * 512];   // [part][hi/lo]
__device__ float g_gi[2][BB][1536];        // x-part gates, layers 1-2
__device__ float g_gh[3][BB][1536];        // h-part gates, layers 0-2
__device__ unsigned g_flags[NCTA];

// ------------------------------ helpers --------------------------------------
__device__ __forceinline__ float sigm(float x) { return 1.f / (1.f + __expf(-x)); }
__device__ __forceinline__ uint32_t smem_u32(const void* p) {
    uint32_t a;
    asm("{ .reg .u64 t; cvta.to.shared.u64 t, %1; cvt.u32.u64 %0, t; }" : "=r"(a) : "l"(p));
    return a;
}
__device__ __forceinline__ void ldsm4(uint32_t a, uint32_t& r0, uint32_t& r1,
                                      uint32_t& r2, uint32_t& r3) {
    asm volatile("ldmatrix.sync.aligned.m8n8.x4.shared.b16 {%0,%1,%2,%3}, [%4];"
                 : "=r"(r0), "=r"(r1), "=r"(r2), "=r"(r3) : "r"(a));
}
__device__ __forceinline__ void mma4(float* d, uint32_t a0, uint32_t a1, uint32_t a2,
                                     uint32_t a3, uint32_t b0, uint32_t b1) {
    asm volatile("mma.sync.aligned.m16n8k16.row.col.f32.f16.f16.f32 "
                 "{%0,%1,%2,%3},{%4,%5,%6,%7},{%8,%9},{%0,%1,%2,%3};"
                 : "+f"(d[0]), "+f"(d[1]), "+f"(d[2]), "+f"(d[3])
                 : "r"(a0), "r"(a1), "r"(a2), "r"(a3), "r"(b0), "r"(b1));
}
__device__ __forceinline__ void cp16(uint32_t dst, const void* src) {
    asm volatile("cp.async.cg.shared.global [%0], [%1], 16;" :: "r"(dst), "l"(src));
}
#define CP_COMMIT() asm volatile("cp.async.commit_group;" ::: "memory")
#define CP_WAIT1()  asm volatile("cp.async.wait_group 1;" ::: "memory")
#define CP_WAIT0()  asm volatile("cp.async.wait_group 0;" ::: "memory")
#define PAIR_BAR(id) asm volatile("bar.sync %0, 64;" :: "r"(id) : "memory")

// ------------------------------ prep kernels ---------------------------------
__global__ void k_zero() {
    long i = (long)blockIdx.x * blockDim.x + threadIdx.x;
    long nf = 3L * 2 * BB * HH;
    float* pf = &g_h_f32[0][0][0][0];
    for (long j = i; j < nf; j += (long)gridDim.x * blockDim.x) pf[j] = 0.f;
    __half* ph = &g_hA[0][0][0];
    long nh = 3L * 2 * BB * HH;
    for (long j = i; j < nh; j += (long)gridDim.x * blockDim.x) ph[j] = __float2half(0.f);
    if (i < NCTA) g_flags[i] = 0u;
}

__global__ void k_ig0(const float* __restrict__ emb, const float* __restrict__ w_ih,
                      const float* __restrict__ bias) {
    int idx = blockIdx.x * blockDim.x + threadIdx.x;
    if (idx >= 65 * 1536) return;
    int tok = idx / 1536, j = idx - tok * 1536;
    const float* e = emb + tok * HH;
    const float* w = w_ih + (long)j * HH;
    float acc = bias[j];
    #pragma unroll 8
    for (int k = 0; k < HH; ++k) acc += e[k] * w[k];
    g_ig0[idx] = acc;
}

__global__ void k_prepw(const float* __restrict__ w_ih, const float* __restrict__ w_hh,
                        const float* __restrict__ w_out) {
    long idx = (long)blockIdx.x * 256 + threadIdx.x;     // 6 * 1536 * 512
    if (idx >= 6L * 1536 * 512) return;
    int k = (int)(idx & 511);
    long r = idx >> 9;
    int row = (int)(r % 1536);
    int part = (int)(r / 1536);
    float v = 0.f;
    if (part == 0)      v = w_hh[(long)row * 512 + k];
    else if (part == 1) v = w_ih[(1536L + row) * 512 + k];
    else if (part == 2) v = w_hh[(1536L + row) * 512 + k];
    else if (part == 3) v = w_ih[(2L * 1536 + row) * 512 + k];
    else if (part == 4) v = w_hh[(2L * 1536 + row) * 512 + k];
    else if (row < 65)  v = w_out[(long)row * 512 + k];
    __half hi = __float2half(v);
    __half lo = __float2half(v - __half2float(hi));
    g_wf16[part][0][(long)row * 512 + k] = hi;
    g_wf16[part][1][(long)row * 512 + k] = lo;
}

// ------------------------------ grid barrier ---------------------------------
__device__ __forceinline__ void grid_barrier(unsigned target, int cta, int tid) {
    __threadfence();
    __syncthreads();
    if (tid == 0) *((volatile unsigned*)&g_flags[cta]) = target;
    if (tid < NCTA) {
        while (*((volatile unsigned*)&g_flags[tid]) < target) { }
    }
    __threadfence();
    __syncthreads();
}

// ------------------------------ GEMM core ------------------------------------
// Pair-local pipeline: warp w (wg0) + warp w (wg1) consume A rows [w*16,w*16+16).
// Each warp stages 8 of those rows per chunk; sync via 2-warp named barrier.
// W persistent in smem (fp16 hi+lo planes), A single fp16 plane.
template <int NTW, int NPH>
__device__ __forceinline__ void gemm_run(
    const __half* __restrict__ A0, const __half* __restrict__ A1,
    uint32_t whi, uint32_t wlo, uint32_t pitchB, int wrow0,
    uint32_t apair, int arow0, int wg, int barid,
    float (&acc)[NPH][NTW][4], int lane)
{
    const int lr = lane & 7, gq = lane >> 3;
    const uint32_t aoff = (uint32_t)((lr + (gq & 1) * 8) * 144 + ((gq >> 1) * 8) * 2);

    auto stage = [&](int cg, int buf) {
        const __half* a = ((cg >> 3) == 0) ? A0 : A1;
        const int kc = cg & 7;
        const uint32_t dst = apair + (uint32_t)buf * 2304 + (uint32_t)(wg * 8) * 144;
        const __half* s = a + (long)(arow0 + wg * 8) * HH + kc * 64;
        #pragma unroll
        for (int i = 0; i < 2; ++i) {
            int e = lane + i * 32;
            int rr = e >> 3, u = e & 7;
            cp16(dst + (uint32_t)(rr * 144 + u * 16), s + rr * HH + u * 8);
        }
        CP_COMMIT();
    };

    const int TOT = NPH * 8;
    stage(0, 0);
    #pragma unroll 1
    for (int cg = 0; cg < TOT; ++cg) {
        const int buf = cg & 1;
        if (cg + 1 < TOT) { stage(cg + 1, buf ^ 1); CP_WAIT1(); }
        else CP_WAIT0();
        PAIR_BAR(barid);                      // chunk cg landed (both warps)
        const uint32_t ab = apair + (uint32_t)buf * 2304;
        const int ph = cg >> 3;
        const int kg = ph * 512 + (cg & 7) * 64;
        #pragma unroll
        for (int ks = 0; ks < 4; ++ks) {
            uint32_t a0, a1, a2, a3;
            ldsm4(ab + aoff + ks * 32, a0, a1, a2, a3);
            const uint32_t kbyte = (uint32_t)(kg + ks * 16 + (gq >> 1) * 8) * 2;
            #pragma unroll
            for (int p2 = 0; p2 < (NTW + 1) / 2; ++p2) {
                uint32_t wo = (uint32_t)(wrow0 + p2 * 16) * pitchB + kbyte;
                uint32_t bh0, bh1, bh2, bh3, bl0, bl1, bl2, bl3;
                ldsm4(whi + wo, bh0, bh1, bh2, bh3);
                ldsm4(wlo + wo, bl0, bl1, bl2, bl3);
                float* d0 = acc[ph][2 * p2];
                mma4(d0, a0, a1, a2, a3, bh0, bh2);
                mma4(d0, a0, a1, a2, a3, bl0, bl2);
                if (2 * p2 + 1 < NTW) {
                    float* d1 = acc[ph][2 * p2 + 1];
                    mma4(d1, a0, a1, a2, a3, bh1, bh3);
                    mma4(d1, a0, a1, a2, a3, bl1, bl3);
                }
            }
        }
        PAIR_BAR(barid);                      // both warps done; buffer reusable
    }
}

template <int NTW>
__device__ __forceinline__ void write_gates(float* __restrict__ gbuf,
                                            const float (*acc)[4],
                                            int n0w, int tid)
{
    const int warp8 = (tid >> 5) & 7, lane = tid & 31;
    const int nb = n0w + (lane & 3) * 2;
    const int b0 = warp8 * 16 + (lane >> 2);
    #pragma unroll
    for (int j = 0; j < NTW; ++j) {
        int n = nb + j * 8;
        *(float2*)(gbuf + (long)b0 * 1536 + n)       = make_float2(acc[j][0], acc[j][1]);
        *(float2*)(gbuf + (long)(b0 + 8) * 1536 + n) = make_float2(acc[j][2], acc[j][3]);
    }
}

// ------------------------------- main kernel ---------------------------------
__global__ void __launch_bounds__(NTHR, 1) k_main(
    const int* __restrict__ x_seq,
    const float* __restrict__ bias, const float* __restrict__ b_n,
    const float* __restrict__ b_out, float* __restrict__ out)
{
    extern __shared__ unsigned char smem[];
    const uint32_t sb = smem_u32(smem);
    const int tid = threadIdx.x;
    const int wg = tid >> 8;
    const int lane = tid & 31, warp8 = (tid >> 5) & 7;
    const int cta = blockIdx.x;

    const uint32_t apair = sb + OFF_A + (uint32_t)warp8 * PAIR_STRIDE;
    const int arow0 = warp8 * 16;
    const int barid = 1 + warp8;

    // ---- role decode ----
    int role, lay = 0, n0 = 0, rows_alloc, rowbase, ktot, p0, p1;
    if (cta < 24) {
        role = 0; lay = 0; n0 = cta * 64; rows_alloc = 64;
        rowbase = wg * 32; ktot = 512; p0 = 0; p1 = 0;
    } else if (cta < 72) {
        role = 1; lay = 1; n0 = (cta - 24) * 32; rows_alloc = 32;
        rowbase = wg * 16; ktot = 1024; p0 = 1; p1 = 2;
    } else if (cta < 120) {
        role = 2; lay = 2; n0 = (cta - 72) * 32; rows_alloc = 32;
        rowbase = wg * 16; ktot = 1024; p0 = 3; p1 = 4;
    } else {
        role = 3; lay = 3; n0 = (cta - 120) * 40; rows_alloc = 48;
        rowbase = wg * 24; ktot = 512; p0 = 5; p1 = 5;
    }
    const int wpitch_e = ktot + 8;
    const uint32_t pitchB = (uint32_t)wpitch_e * 2;
    const uint32_t wplane = (uint32_t)rows_alloc * pitchB;
    const uint32_t whi = sb + OFF_W, wlo = whi + wplane;
    const int lr = lane & 7, gq = lane >> 3;
    const int wrow0 = rowbase + lr + (gq & 1) * 8;

    // ---- persistent weight load (once) ----
    {
        __half* whs = (__half*)(smem + OFF_W);
        __half* wls = (__half*)(smem + OFF_W + wplane);
        for (int e = tid; e < rows_alloc * ktot; e += NTHR) {
            int r = e / ktot, k = e - r * ktot;
            int grow = n0 + r; if (grow > 1535) grow = 0;
            int part = (k < 512) ? p0 : p1;
            int kk = k & 511;
            whs[r * wpitch_e + k] = g_wf16[part][0][(long)grow * 512 + kk];
            wls[r * wpitch_e + k] = g_wf16[part][1][(long)grow * 512 + kk];
        }
    }
    __syncthreads();

    const int gtid = cta * NTHR + tid;

    for (int s = 0; s < TT + 3; ++s) {
        const int rd = (s + 1) & 1, wr = s & 1;

        // ================= phase 1: GEMMs =====================================
        bool active;
        if (role == 0)      active = (s < TT);
        else if (role == 1) active = (s >= 1 && s <= TT);
        else if (role == 2) active = (s >= 2 && s <= TT + 1);
        else                active = (s >= 3);

        if (active) {
            if (role == 0) {
                float acc[1][4][4] = {};
                gemm_run<4, 1>(g_hA[0][rd], g_hA[0][rd], whi, wlo, pitchB, wrow0,
                               apair, arow0, wg, barid, acc, lane);
                write_gates<4>(&g_gh[0][0][0], acc[0], n0 + rowbase, tid);
            } else if (role == 1 || role == 2) {
                float acc[2][2][4] = {};
                gemm_run<2, 2>(g_hA[lay - 1][rd], g_hA[lay][rd], whi, wlo, pitchB, wrow0,
                               apair, arow0, wg, barid, acc, lane);
                write_gates<2>(&g_gi[lay - 1][0][0], acc[0], n0 + rowbase, tid);
                write_gates<2>(&g_gh[lay][0][0],     acc[1], n0 + rowbase, tid);
            } else {
                const int t = s - 3;
                const int nb = n0 + rowbase + (lane & 3) * 2;
                const int b0 = warp8 * 16 + (lane >> 2);
                float accbuf[3][4] = {};
                int ntw_here;
                if (wg == 0) {
                    float acc[1][3][4] = {};
                    gemm_run<3, 1>(g_hA[2][rd], g_hA[2][rd], whi, wlo, pitchB, wrow0,
                                   apair, arow0, wg, barid, acc, lane);
                    #pragma unroll
                    for (int j = 0; j < 3; ++j)
                        #pragma unroll
                        for (int q = 0; q < 4; ++q) accbuf[j][q] = acc[0][j][q];
                    ntw_here = 3;
                } else {
                    float acc[1][2][4] = {};
                    gemm_run<2, 1>(g_hA[2][rd], g_hA[2][rd], whi, wlo, pitchB, wrow0,
                                   apair, arow0, wg, barid, acc, lane);
                    #pragma unroll
                    for (int j = 0; j < 2; ++j)
                        #pragma unroll
                        for (int q = 0; q < 4; ++q) accbuf[j][q] = acc[0][j][q];
                    ntw_here = 2;
                }
                for (int j = 0; j < ntw_here; ++j) {
                    int n = nb + j * 8;
                    #pragma unroll
                    for (int dn = 0; dn < 2; ++dn) {
                        int v = n + dn;
                        if (v < 65) {
                            float bo = __ldg(b_out + v);
                            out[((long)b0 * TT + t) * 65 + v]       = accbuf[j][dn]     + bo;
                            out[((long)(b0 + 8) * TT + t) * 65 + v] = accbuf[j][2 + dn] + bo;
                        }
                    }
                }
            }
        }

        grid_barrier((unsigned)(2 * s + 1), cta, tid);

        // ================= phase 2: GRU nonlinearity -> h slabs ==============
        if (s < TT) {                       // layer 0, t = s
            const int t = s;
            for (int e = gtid; e < BB * HH; e += GT) {
                int b = e >> 9, g = e & 511;
                int tok = __ldg(x_seq + (long)b * TT + t);
                const float* ig = g_ig0 + (long)tok * 1536;
                const float* gh = &g_gh[0][0][0] + (long)b * 1536;
                float hr = __ldcv(gh + g);
                float hz = __ldcv(gh + 512 + g);
                float hn = __ldcv(gh + 1024 + g);
                float r = sigm(ig[g] + hr);
                float z = sigm(ig[512 + g] + hz);
                float n = tanhf(ig[1024 + g] + r * (hn + b_n[g]));
                float hp = g_h_f32[0][rd][b][g];
                float h = n + z * (hp - n);
                g_h_f32[0][wr][b][g] = h;
                g_hA[0][wr][e] = __float2half(h);
            }
        }
        #pragma unroll
        for (int ly = 1; ly <= 2; ++ly) {
            if (s >= ly && s <= TT + ly - 1) {
                const float* bl = bias + (long)ly * 1536;
                const float* bnl = b_n + (long)ly * 512;
                const float* gib = &g_gi[ly - 1][0][0];
                const float* ghb = &g_gh[ly][0][0];
                for (int e = gtid; e < BB * HH; e += GT) {
                    int b = e >> 9, g = e & 511;
                    const float* gi = gib + (long)b * 1536;
                    const float* gh = ghb + (long)b * 1536;
                    float ir = __ldcv(gi + g)         + bl[g];
                    float iz = __ldcv(gi + 512 + g)   + bl[512 + g];
                    float in_ = __ldcv(gi + 1024 + g) + bl[1024 + g];
                    float hr = __ldcv(gh + g);
                    float hz = __ldcv(gh + 512 + g);
                    float hn = __ldcv(gh + 1024 + g);
                    float r = sigm(ir + hr);
                    float z = sigm(iz + hz);
                    float n = tanhf(in_ + r * (hn + bnl[g]));
                    float hp = g_h_f32[ly][rd][b][g];
                    float h = n + z * (hp - n);
                    g_h_f32[ly][wr][b][g] = h;
                    g_hA[ly][wr][e] = __float2half(h);
                }
            }
        }

        grid_barrier((unsigned)(2 * s + 2), cta, tid);
    }
}

// --------------------------------- launch ------------------------------------
extern "C" void kernel_launch(void* const* d_in, const int* in_sizes, int n_in,
                              void* d_out, int out_size) {
    const int*   x_seq = (const int*)  d_in[0];
    const float* emb   = (const float*)d_in[1];
    const float* w_ih  = (const float*)d_in[2];
    const float* w_hh  = (const float*)d_in[3];
    const float* b     = (const float*)d_in[4];
    const float* b_n   = (const float*)d_in[5];
    const float* w_out = (const float*)d_in[6];
    const float* b_out = (const float*)d_in[7];
    float* out = (float*)d_out;

    cudaFuncSetAttribute(k_main, cudaFuncAttributeMaxDynamicSharedMemorySize, SMEM_BYTES);

    k_zero<<<512, 256>>>();
    k_ig0<<<(65 * 1536 + 255) / 256, 256>>>(emb, w_ih, b);
    k_prepw<<<(int)((6L * 1536 * 512 + 255) / 256), 256>>>(w_ih, w_hh, w_out);
    k_main<<<NCTA, NTHR, SMEM_BYTES>>>(x_seq, b, b_n, b_out, out);
}

// round 8
// speedup vs baseline: 1.1376x; 1.1376x over previous
#include <cuda_runtime.h>
#include <cuda_fp16.h>
#include <cstdint>
#include <math.h>

#define BB 128
#define TT 1024
#define HH 512
#define NCTA 122
#define NTHR 512
#define GT   (NCTA * NTHR)

// smem layout (bytes)
#define ABUF 18432                   // one chunk: 128 rows * 144B
#define OFF_A 0                      // 3 buffers -> 55296
#define OFF_W 55296                  // persistent weights (max 133120)
#define SMEM_BYTES 188672

// ------------------------- persistent device state ---------------------------
__device__ float g_ig0[65 * 1536];
__device__ float g_h_f32[3][2][BB][HH];
__device__ __align__(16) __half g_hA[3][2][BB * HH];        // fp16 h slabs
__device__ __align__(16) __half g_wf16[6][2][1536 * 512];   // [part][hi/lo]
__device__ float g_gi[2][BB][1536];        // x-part gates, layers 1-2
__device__ float g_gh[3][BB][1536];        // h-part gates, layers 0-2
__device__ unsigned g_flags[NCTA];

// ------------------------------ helpers --------------------------------------
__device__ __forceinline__ float sigm(float x) { return 1.f / (1.f + __expf(-x)); }
__device__ __forceinline__ uint32_t smem_u32(const void* p) {
    uint32_t a;
    asm("{ .reg .u64 t; cvta.to.shared.u64 t, %1; cvt.u32.u64 %0, t; }" : "=r"(a) : "l"(p));
    return a;
}
__device__ __forceinline__ void ldsm4(uint32_t a, uint32_t& r0, uint32_t& r1,
                                      uint32_t& r2, uint32_t& r3) {
    asm volatile("ldmatrix.sync.aligned.m8n8.x4.shared.b16 {%0,%1,%2,%3}, [%4];"
                 : "=r"(r0), "=r"(r1), "=r"(r2), "=r"(r3) : "r"(a));
}
__device__ __forceinline__ void mma4(float* d, uint32_t a0, uint32_t a1, uint32_t a2,
                                     uint32_t a3, uint32_t b0, uint32_t b1) {
    asm volatile("mma.sync.aligned.m16n8k16.row.col.f32.f16.f16.f32 "
                 "{%0,%1,%2,%3},{%4,%5,%6,%7},{%8,%9},{%0,%1,%2,%3};"
                 : "+f"(d[0]), "+f"(d[1]), "+f"(d[2]), "+f"(d[3])
                 : "r"(a0), "r"(a1), "r"(a2), "r"(a3), "r"(b0), "r"(b1));
}
__device__ __forceinline__ void cp16(uint32_t dst, const void* src) {
    asm volatile("cp.async.cg.shared.global [%0], [%1], 16;" :: "r"(dst), "l"(src));
}
#define CP_COMMIT() asm volatile("cp.async.commit_group;" ::: "memory")
#define CP_WAIT1()  asm volatile("cp.async.wait_group 1;" ::: "memory")
#define CP_WAIT0()  asm volatile("cp.async.wait_group 0;" ::: "memory")

// ------------------------------ prep kernels ---------------------------------
__global__ void k_zero() {
    long i = (long)blockIdx.x * blockDim.x + threadIdx.x;
    long nf = 3L * 2 * BB * HH;
    float* pf = &g_h_f32[0][0][0][0];
    for (long j = i; j < nf; j += (long)gridDim.x * blockDim.x) pf[j] = 0.f;
    __half* ph = &g_hA[0][0][0];
    long nh = 3L * 2 * BB * HH;
    for (long j = i; j < nh; j += (long)gridDim.x * blockDim.x) ph[j] = __float2half(0.f);
    if (i < NCTA) g_flags[i] = 0u;
}

__global__ void k_ig0(const float* __restrict__ emb, const float* __restrict__ w_ih,
                      const float* __restrict__ bias) {
    int idx = blockIdx.x * blockDim.x + threadIdx.x;
    if (idx >= 65 * 1536) return;
    int tok = idx / 1536, j = idx - tok * 1536;
    const float* e = emb + tok * HH;
    const float* w = w_ih + (long)j * HH;
    float acc = bias[j];
    #pragma unroll 8
    for (int k = 0; k < HH; ++k) acc += e[k] * w[k];
    g_ig0[idx] = acc;
}

__global__ void k_prepw(const float* __restrict__ w_ih, const float* __restrict__ w_hh,
                        const float* __restrict__ w_out) {
    long idx = (long)blockIdx.x * 256 + threadIdx.x;     // 6 * 1536 * 512
    if (idx >= 6L * 1536 * 512) return;
    int k = (int)(idx & 511);
    long r = idx >> 9;
    int row = (int)(r % 1536);
    int part = (int)(r / 1536);
    float v = 0.f;
    if (part == 0)      v = w_hh[(long)row * 512 + k];
    else if (part == 1) v = w_ih[(1536L + row) * 512 + k];
    else if (part == 2) v = w_hh[(1536L + row) * 512 + k];
    else if (part == 3) v = w_ih[(2L * 1536 + row) * 512 + k];
    else if (part == 4) v = w_hh[(2L * 1536 + row) * 512 + k];
    else if (row < 65)  v = w_out[(long)row * 512 + k];
    __half hi = __float2half(v);
    __half lo = __float2half(v - __half2float(hi));
    g_wf16[part][0][(long)row * 512 + k] = hi;
    g_wf16[part][1][(long)row * 512 + k] = lo;
}

// ------------------------------ grid barrier ---------------------------------
__device__ __forceinline__ void grid_barrier(unsigned target, int cta, int tid) {
    __threadfence();
    __syncthreads();
    if (tid == 0) *((volatile unsigned*)&g_flags[cta]) = target;
    if (tid < NCTA) {
        while (*((volatile unsigned*)&g_flags[tid]) < target) { }
    }
    __threadfence();
    __syncthreads();
}

// ------------------------------ GEMM core ------------------------------------
// Block-cooperative staging, 3 smem buffers, 1 __syncthreads per chunk.
// CHUNK ORDER IS STAGGERED by `offset` so different CTAs never hit the same
// L2 lines at the same instant (accumulation is order-independent).
template <int NTW, int NPH>
__device__ __forceinline__ void gemm_run(
    const __half* __restrict__ A0, const __half* __restrict__ A1,
    uint32_t whi, uint32_t wlo, uint32_t pitchB, int wrow0,
    uint32_t abase, int offset, float (&acc)[NPH][NTW][4], int tid)
{
    const int warp8 = (tid >> 5) & 7, lane = tid & 31;
    const int lr = lane & 7, gq = lane >> 3;
    const uint32_t aoff = (uint32_t)((warp8 * 16 + lr + (gq & 1) * 8) * 144
                                     + ((gq >> 1) * 8) * 2);
    const int TOT = NPH * 8;

    auto stage = [&](int j) {
        int cg = (j + offset) & (TOT - 1);
        const __half* a = ((cg >> 3) == 0) ? A0 : A1;
        int kc = cg & 7;
        uint32_t dst = abase + (uint32_t)(j % 3) * ABUF;
        const __half* s = a + kc * 64;
        #pragma unroll
        for (int i = 0; i < 2; ++i) {
            int e = tid + i * NTHR;
            int rr = e >> 3, u = e & 7;
            cp16(dst + (uint32_t)(rr * 144 + u * 16), s + (long)rr * HH + u * 8);
        }
        CP_COMMIT();
    };

    stage(0); stage(1);
    #pragma unroll 1
    for (int j = 0; j < TOT; ++j) {
        if (j == TOT - 1) CP_WAIT0(); else CP_WAIT1();
        __syncthreads();
        if (j + 2 < TOT) stage(j + 2);
        const int cg = (j + offset) & (TOT - 1);
        const uint32_t ab = abase + (uint32_t)(j % 3) * ABUF;
        const int ph = cg >> 3;
        const int kg = ph * 512 + (cg & 7) * 64;
        #pragma unroll
        for (int ks = 0; ks < 4; ++ks) {
            uint32_t a0, a1, a2, a3;
            ldsm4(ab + aoff + ks * 32, a0, a1, a2, a3);
            const uint32_t kbyte = (uint32_t)(kg + ks * 16 + (gq >> 1) * 8) * 2;
            #pragma unroll
            for (int p2 = 0; p2 < (NTW + 1) / 2; ++p2) {
                uint32_t wo = (uint32_t)(wrow0 + p2 * 16) * pitchB + kbyte;
                uint32_t bh0, bh1, bh2, bh3, bl0, bl1, bl2, bl3;
                ldsm4(whi + wo, bh0, bh1, bh2, bh3);
                ldsm4(wlo + wo, bl0, bl1, bl2, bl3);
                float* d0 = acc[ph][2 * p2];
                mma4(d0, a0, a1, a2, a3, bh0, bh2);
                mma4(d0, a0, a1, a2, a3, bl0, bl2);
                if (2 * p2 + 1 < NTW) {
                    float* d1 = acc[ph][2 * p2 + 1];
                    mma4(d1, a0, a1, a2, a3, bh1, bh3);
                    mma4(d1, a0, a1, a2, a3, bl1, bl3);
                }
            }
        }
    }
    __syncthreads();
}

template <int NTW>
__device__ __forceinline__ void write_gates(float* __restrict__ gbuf,
                                            const float (*acc)[4],
                                            int n0w, int tid)
{
    const int warp8 = (tid >> 5) & 7, lane = tid & 31;
    const int nb = n0w + (lane & 3) * 2;
    const int b0 = warp8 * 16 + (lane >> 2);
    #pragma unroll
    for (int j = 0; j < NTW; ++j) {
        int n = nb + j * 8;
        *(float2*)(gbuf + (long)b0 * 1536 + n)       = make_float2(acc[j][0], acc[j][1]);
        *(float2*)(gbuf + (long)(b0 + 8) * 1536 + n) = make_float2(acc[j][2], acc[j][3]);
    }
}

// ------------------------------- main kernel ---------------------------------
__global__ void __launch_bounds__(NTHR, 1) k_main(
    const int* __restrict__ x_seq,
    const float* __restrict__ bias, const float* __restrict__ b_n,
    const float* __restrict__ b_out, float* __restrict__ out)
{
    extern __shared__ unsigned char smem[];
    const uint32_t sb = smem_u32(smem);
    const uint32_t abase = sb + OFF_A;
    const int tid = threadIdx.x;
    const int wg = tid >> 8;
    const int lane = tid & 31, warp8 = (tid >> 5) & 7;
    const int cta = blockIdx.x;

    // ---- role decode ----
    int role, lay = 0, n0 = 0, rows_alloc, ntw, rowbase, ktot, p0, p1;
    if (cta < 24) {
        role = 0; lay = 0; n0 = cta * 64; rows_alloc = 64;
        ntw = 4; rowbase = wg * 32; ktot = 512; p0 = 0; p1 = 0;
    } else if (cta < 72) {
        role = 1; lay = 1; n0 = (cta - 24) * 32; rows_alloc = 32;
        ntw = 2; rowbase = wg * 16; ktot = 1024; p0 = 1; p1 = 2;
    } else if (cta < 120) {
        role = 2; lay = 2; n0 = (cta - 72) * 32; rows_alloc = 32;
        ntw = 2; rowbase = wg * 16; ktot = 1024; p0 = 3; p1 = 4;
    } else {
        role = 3; lay = 3; n0 = (cta - 120) * 40; rows_alloc = 48;
        ntw = 3; rowbase = wg * 24; ktot = 512; p0 = 5; p1 = 5;
    }
    const int wpitch_e = ktot + 8;
    const uint32_t pitchB = (uint32_t)wpitch_e * 2;
    const uint32_t wplane = (uint32_t)rows_alloc * pitchB;
    const uint32_t whi = sb + OFF_W, wlo = whi + wplane;
    const int lr = lane & 7, gq = lane >> 3;
    const int wrow0 = rowbase + lr + (gq & 1) * 8;
    const int chTOT = (role == 1 || role == 2) ? 16 : 8;
    const int choff = (cta * 5) & (chTOT - 1);

    // ---- persistent weight load (once) ----
    {
        __half* whs = (__half*)(smem + OFF_W);
        __half* wls = (__half*)(smem + OFF_W + wplane);
        for (int e = tid; e < rows_alloc * ktot; e += NTHR) {
            int r = e / ktot, k = e - r * ktot;
            int grow = n0 + r; if (grow > 1535) grow = 0;
            int part = (k < 512) ? p0 : p1;
            int kk = k & 511;
            whs[r * wpitch_e + k] = g_wf16[part][0][(long)grow * 512 + kk];
            wls[r * wpitch_e + k] = g_wf16[part][1][(long)grow * 512 + kk];
        }
    }
    __syncthreads();

    const int gtid = cta * NTHR + tid;

    for (int s = 0; s < TT + 3; ++s) {
        const int rd = (s + 1) & 1, wr = s & 1;

        // ================= phase 1: GEMMs =====================================
        bool active;
        if (role == 0)      active = (s < TT);
        else if (role == 1) active = (s >= 1 && s <= TT);
        else if (role == 2) active = (s >= 2 && s <= TT + 1);
        else                active = (s >= 3);

        if (active) {
            if (role == 0) {
                float acc[1][4][4] = {};
                gemm_run<4, 1>(g_hA[0][rd], g_hA[0][rd], whi, wlo, pitchB, wrow0,
                               abase, choff, acc, tid);
                write_gates<4>(&g_gh[0][0][0], acc[0], n0 + rowbase, tid);
            } else if (role == 1 || role == 2) {
                float acc[2][2][4] = {};
                gemm_run<2, 2>(g_hA[lay - 1][rd], g_hA[lay][rd], whi, wlo, pitchB, wrow0,
                               abase, choff, acc, tid);
                write_gates<2>(&g_gi[lay - 1][0][0], acc[0], n0 + rowbase, tid);
                write_gates<2>(&g_gh[lay][0][0],     acc[1], n0 + rowbase, tid);
            } else {
                float acc[1][3][4] = {};
                gemm_run<3, 1>(g_hA[2][rd], g_hA[2][rd], whi, wlo, pitchB, wrow0,
                               abase, choff, acc, tid);
                const int t = s - 3;
                const int nb = n0 + rowbase + (lane & 3) * 2;
                const int b0 = warp8 * 16 + (lane >> 2);
                #pragma unroll
                for (int j = 0; j < 3; ++j) {
                    int n = nb + j * 8;
                    #pragma unroll
                    for (int dn = 0; dn < 2; ++dn) {
                        int v = n + dn;
                        if (v < 65) {
                            float bo = __ldg(b_out + v);
                            out[((long)b0 * TT + t) * 65 + v]       = acc[0][j][dn]     + bo;
                            out[((long)(b0 + 8) * TT + t) * 65 + v] = acc[0][j][2 + dn] + bo;
                        }
                    }
                }
            }
        }

        grid_barrier((unsigned)(2 * s + 1), cta, tid);

        // ================= phase 2: GRU nonlinearity -> h slabs ==============
        if (s < TT) {                       // layer 0, t = s
            const int t = s;
            for (int e = gtid; e < BB * HH; e += GT) {
                int b = e >> 9, g = e & 511;
                int tok = __ldg(x_seq + (long)b * TT + t);
                const float* ig = g_ig0 + (long)tok * 1536;
                const float* gh = &g_gh[0][0][0] + (long)b * 1536;
                float hr = __ldcv(gh + g);
                float hz = __ldcv(gh + 512 + g);
                float hn = __ldcv(gh + 1024 + g);
                float r = sigm(ig[g] + hr);
                float z = sigm(ig[512 + g] + hz);
                float n = tanhf(ig[1024 + g] + r * (hn + b_n[g]));
                float hp = g_h_f32[0][rd][b][g];
                float h = n + z * (hp - n);
                g_h_f32[0][wr][b][g] = h;
                g_hA[0][wr][e] = __float2half(h);
            }
        }
        #pragma unroll
        for (int ly = 1; ly <= 2; ++ly) {
            if (s >= ly && s <= TT + ly - 1) {
                const float* bl = bias + (long)ly * 1536;
                const float* bnl = b_n + (long)ly * 512;
                const float* gib = &g_gi[ly - 1][0][0];
                const float* ghb = &g_gh[ly][0][0];
                for (int e = gtid; e < BB * HH; e += GT) {
                    int b = e >> 9, g = e & 511;
                    const float* gi = gib + (long)b * 1536;
                    const float* gh = ghb + (long)b * 1536;
                    float ir = __ldcv(gi + g)         + bl[g];
                    float iz = __ldcv(gi + 512 + g)   + bl[512 + g];
                    float in_ = __ldcv(gi + 1024 + g) + bl[1024 + g];
                    float hr = __ldcv(gh + g);
                    float hz = __ldcv(gh + 512 + g);
                    float hn = __ldcv(gh + 1024 + g);
                    float r = sigm(ir + hr);
                    float z = sigm(iz + hz);
                    float n = tanhf(in_ + r * (hn + bnl[g]));
                    float hp = g_h_f32[ly][rd][b][g];
                    float h = n + z * (hp - n);
                    g_h_f32[ly][wr][b][g] = h;
                    g_hA[ly][wr][e] = __float2half(h);
                }
            }
        }

        grid_barrier((unsigned)(2 * s + 2), cta, tid);
    }
}

// --------------------------------- launch ------------------------------------
extern "C" void kernel_launch(void* const* d_in, const int* in_sizes, int n_in,
                              void* d_out, int out_size) {
    const int*   x_seq = (const int*)  d_in[0];
    const float* emb   = (const float*)d_in[1];
    const float* w_ih  = (const float*)d_in[2];
    const float* w_hh  = (const float*)d_in[3];
    const float* b     = (const float*)d_in[4];
    const float* b_n   = (const float*)d_in[5];
    const float* w_out = (const float*)d_in[6];
    const float* b_out = (const float*)d_in[7];
    float* out = (float*)d_out;

    cudaFuncSetAttribute(k_main, cudaFuncAttributeMaxDynamicSharedMemorySize, SMEM_BYTES);

    k_zero<<<512, 256>>>();
    k_ig0<<<(65 * 1536 + 255) / 256, 256>>>(emb, w_ih, b);
    k_prepw<<<(int)((6L * 1536 * 512 + 255) / 256), 256>>>(w_ih, w_hh, w_out);
    k_main<<<NCTA, NTHR, SMEM_BYTES>>>(x_seq, b, b_n, b_out, out);
}

// round 9
// speedup vs baseline: 1.5425x; 1.3559x over previous
#include <cuda_runtime.h>
#include <cuda_fp16.h>
#include <cstdint>
#include <math.h>

#define BB 128
#define TT 1024
#define HH 512
#define NCTA 99
#define NTHR 512

// smem: 3 buffers of (A 18432 + Whi 6912 + Wlo 6912) + rowmap
#define ABYTES 18432
#define WBYTES 6912
#define BUFSTR (ABYTES + 2 * WBYTES)        // 32256
#define OFF_MAP (3 * BUFSTR)                // 96768
#define SMEM_BYTES (OFF_MAP + 256)

// ------------------------- persistent device state ---------------------------
__device__ float g_ig0[65 * 1536];                       // layer0 igates + bias
__device__ __align__(16) __half g_hA[3][2][BB * HH];     // fp16 h slabs [lay][pp]
__device__ __align__(16) __half g_wf16[6][2][1536 * 512];// [part][hi/lo]
__device__ unsigned g_flags[NCTA];
__device__ unsigned g_gen;

// ------------------------------ helpers --------------------------------------
__device__ __forceinline__ float sigm(float x) { return 1.f / (1.f + __expf(-x)); }
__device__ __forceinline__ uint32_t smem_u32(const void* p) {
    uint32_t a;
    asm("{ .reg .u64 t; cvta.to.shared.u64 t, %1; cvt.u32.u64 %0, t; }" : "=r"(a) : "l"(p));
    return a;
}
__device__ __forceinline__ void ldsm4(uint32_t a, uint32_t& r0, uint32_t& r1,
                                      uint32_t& r2, uint32_t& r3) {
    asm volatile("ldmatrix.sync.aligned.m8n8.x4.shared.b16 {%0,%1,%2,%3}, [%4];"
                 : "=r"(r0), "=r"(r1), "=r"(r2), "=r"(r3) : "r"(a));
}
__device__ __forceinline__ void ldsm2(uint32_t a, uint32_t& r0, uint32_t& r1) {
    asm volatile("ldmatrix.sync.aligned.m8n8.x2.shared.b16 {%0,%1}, [%2];"
                 : "=r"(r0), "=r"(r1) : "r"(a));
}
__device__ __forceinline__ void mma4(float* d, uint32_t a0, uint32_t a1, uint32_t a2,
                                     uint32_t a3, uint32_t b0, uint32_t b1) {
    asm volatile("mma.sync.aligned.m16n8k16.row.col.f32.f16.f16.f32 "
                 "{%0,%1,%2,%3},{%4,%5,%6,%7},{%8,%9},{%0,%1,%2,%3};"
                 : "+f"(d[0]), "+f"(d[1]), "+f"(d[2]), "+f"(d[3])
                 : "r"(a0), "r"(a1), "r"(a2), "r"(a3), "r"(b0), "r"(b1));
}
__device__ __forceinline__ void cp16(uint32_t dst, const void* src) {
    asm volatile("cp.async.cg.shared.global [%0], [%1], 16;" :: "r"(dst), "l"(src));
}
#define CP_COMMIT() asm volatile("cp.async.commit_group;" ::: "memory")
#define CP_WAIT1()  asm volatile("cp.async.wait_group 1;" ::: "memory")
#define CP_WAIT0()  asm volatile("cp.async.wait_group 0;" ::: "memory")

// ------------------------------ prep kernels ---------------------------------
__global__ void k_zero() {
    long i = (long)blockIdx.x * blockDim.x + threadIdx.x;
    __half* ph = &g_hA[0][0][0];
    long nh = 3L * 2 * BB * HH;
    for (long j = i; j < nh; j += (long)gridDim.x * blockDim.x) ph[j] = __float2half(0.f);
    if (i < NCTA) g_flags[i] = 0u;
    if (i == 0) g_gen = 0u;
}

__global__ void k_ig0(const float* __restrict__ emb, const float* __restrict__ w_ih,
                      const float* __restrict__ bias) {
    int idx = blockIdx.x * blockDim.x + threadIdx.x;
    if (idx >= 65 * 1536) return;
    int tok = idx / 1536, j = idx - tok * 1536;
    const float* e = emb + tok * HH;
    const float* w = w_ih + (long)j * HH;
    float acc = bias[j];
    #pragma unroll 8
    for (int k = 0; k < HH; ++k) acc += e[k] * w[k];
    g_ig0[idx] = acc;
}

__global__ void k_prepw(const float* __restrict__ w_ih, const float* __restrict__ w_hh,
                        const float* __restrict__ w_out) {
    long idx = (long)blockIdx.x * 256 + threadIdx.x;     // 6 * 1536 * 512
    if (idx >= 6L * 1536 * 512) return;
    int k = (int)(idx & 511);
    long r = idx >> 9;
    int row = (int)(r % 1536);
    int part = (int)(r / 1536);
    float v = 0.f;
    if (part == 0)      v = w_hh[(long)row * 512 + k];
    else if (part == 1) v = w_ih[(1536L + row) * 512 + k];
    else if (part == 2) v = w_hh[(1536L + row) * 512 + k];
    else if (part == 3) v = w_ih[(2L * 1536 + row) * 512 + k];
    else if (part == 4) v = w_hh[(2L * 1536 + row) * 512 + k];
    else if (row < 65)  v = w_out[(long)row * 512 + k];
    __half hi = __float2half(v);
    __half lo = __float2half(v - __half2float(hi));
    g_wf16[part][0][(long)row * 512 + k] = hi;
    g_wf16[part][1][(long)row * 512 + k] = lo;
}

// ---------------- hierarchical grid barrier (low-contention) -----------------
__device__ __forceinline__ void grid_barrier(unsigned target, int cta, int tid) {
    __syncthreads();
    __threadfence();
    if (tid == 0) *((volatile unsigned*)&g_flags[cta]) = target;
    if (cta == 0) {
        if (tid < NCTA) {
            while (*((volatile unsigned*)&g_flags[tid]) < target) { }
        }
        __syncthreads();
        if (tid == 0) { __threadfence(); *((volatile unsigned*)&g_gen) = target; }
    }
    if (tid == 0) {
        while (*((volatile unsigned*)&g_gen) < target) { }
    }
    __syncthreads();
}

// ------------------------------ GEMM core ------------------------------------
// MODE 0: layer CTA (wg row-block = wg*24: r/z via x4, n via x2) -> 3 tiles
// MODE 1: out CTA wg0 (rows 0-15 via x4) -> tiles 0,1
// MODE 2: out CTA wg1 (rows 16-23 via x2) -> tile 2
template <int MODE, int NPH>
__device__ __forceinline__ void gemm_run(
    const __half* __restrict__ A0, const __half* __restrict__ A1,
    const __half* __restrict__ W0h, const __half* __restrict__ W0l,
    const __half* __restrict__ W1h, const __half* __restrict__ W1l,
    int rows_used, const int* __restrict__ rowmap, uint32_t sbuf, int choff,
    float (&acc)[NPH][3][4], int tid, int wg)
{
    const int lane = tid & 31, warp8 = (tid >> 5) & 7;
    const int lr = lane & 7, gq = lane >> 3;
    const uint32_t aoff = (uint32_t)((warp8 * 16 + lr + (gq & 1) * 8) * 144
                                     + (gq >> 1) * 16);
    const int wrowbase = (MODE == 0) ? wg * 24 : 0;
    const uint32_t w4off = (uint32_t)((wrowbase + lr + (gq & 1) * 8) * 144
                                      + (gq >> 1) * 16);
    const uint32_t w2off = (uint32_t)((wrowbase + 16 + lr) * 144
                                      + ((lane >> 3) & 1) * 16);
    const int TOT = NPH * 8;

    auto stage = [&](int j) {
        int cg = (j + choff) & (TOT - 1);
        int ph = cg >> 3, kc = cg & 7;
        uint32_t buf = sbuf + (uint32_t)(j % 3) * BUFSTR;
        const __half* a = ph ? A1 : A0;
        const __half* s0 = a + kc * 64;
        #pragma unroll
        for (int i = 0; i < 2; ++i) {
            int e = tid + i * NTHR;
            int rr = e >> 3, u = e & 7;
            cp16(buf + (uint32_t)(rr * 144 + u * 16), s0 + (long)rr * HH + u * 8);
        }
        const __half* wh = ph ? W1h : W0h;
        const __half* wl = ph ? W1l : W0l;
        int tot = rows_used * 8;
        for (int e = tid; e < 2 * tot; e += NTHR) {
            int p = (e >= tot) ? 1 : 0;
            int e2 = e - p * tot;
            int rr = e2 >> 3, u = e2 & 7;
            cp16(buf + ABYTES + (uint32_t)(p * WBYTES + rr * 144 + u * 16),
                 (p ? wl : wh) + (long)rowmap[rr] * HH + kc * 64 + u * 8);
        }
        CP_COMMIT();
    };

    stage(0); stage(1);
    #pragma unroll 1
    for (int j = 0; j < TOT; ++j) {
        if (j == TOT - 1) CP_WAIT0(); else CP_WAIT1();
        __syncthreads();
        if (j + 2 < TOT) stage(j + 2);
        const int cg = (j + choff) & (TOT - 1);
        const int ph = cg >> 3;
        const uint32_t buf = sbuf + (uint32_t)(j % 3) * BUFSTR;
        const uint32_t wh = buf + ABYTES, wl = wh + WBYTES;
        #pragma unroll
        for (int ks = 0; ks < 4; ++ks) {
            uint32_t a0, a1, a2, a3;
            ldsm4(buf + aoff + ks * 32, a0, a1, a2, a3);
            if (MODE == 0) {
                uint32_t h0, h1, h2, h3, h4v, h5, l0, l1, l2, l3, l4v, l5;
                ldsm4(wh + w4off + ks * 32, h0, h1, h2, h3);
                ldsm2(wh + w2off + ks * 32, h4v, h5);
                ldsm4(wl + w4off + ks * 32, l0, l1, l2, l3);
                ldsm2(wl + w2off + ks * 32, l4v, l5);
                mma4(acc[ph][0], a0, a1, a2, a3, h0, h2);
                mma4(acc[ph][0], a0, a1, a2, a3, l0, l2);
                mma4(acc[ph][1], a0, a1, a2, a3, h1, h3);
                mma4(acc[ph][1], a0, a1, a2, a3, l1, l3);
                mma4(acc[ph][2], a0, a1, a2, a3, h4v, h5);
                mma4(acc[ph][2], a0, a1, a2, a3, l4v, l5);
            } else if (MODE == 1) {
                uint32_t h0, h1, h2, h3, l0, l1, l2, l3;
                ldsm4(wh + w4off + ks * 32, h0, h1, h2, h3);
                ldsm4(wl + w4off + ks * 32, l0, l1, l2, l3);
                mma4(acc[ph][0], a0, a1, a2, a3, h0, h2);
                mma4(acc[ph][0], a0, a1, a2, a3, l0, l2);
                mma4(acc[ph][1], a0, a1, a2, a3, h1, h3);
                mma4(acc[ph][1], a0, a1, a2, a3, l1, l3);
            } else {
                uint32_t h4v, h5, l4v, l5;
                ldsm2(wh + w2off + ks * 32, h4v, h5);
                ldsm2(wl + w2off + ks * 32, l4v, l5);
                mma4(acc[ph][2], a0, a1, a2, a3, h4v, h5);
                mma4(acc[ph][2], a0, a1, a2, a3, l4v, l5);
            }
        }
    }
    __syncthreads();
}

// ------------------------------- main kernel ---------------------------------
__global__ void __launch_bounds__(NTHR, 1) k_main(
    const int* __restrict__ x_seq,
    const float* __restrict__ bias, const float* __restrict__ b_n,
    const float* __restrict__ b_out, float* __restrict__ out)
{
    extern __shared__ unsigned char smem[];
    const uint32_t sbuf = smem_u32(smem);
    int* rowmap = (int*)(smem + OFF_MAP);
    const int tid = threadIdx.x;
    const int wg = tid >> 8;
    const int lane = tid & 31, warp8 = (tid >> 5) & 7;
    const int cta = blockIdx.x;

    // ---- role decode ----
    int role, lay = 0, n0 = 0, vbase = 0, rows_used, TOTC;
    const __half *W0h, *W0l, *W1h, *W1l;
    if (cta < 32) {
        role = 0; lay = 0; n0 = cta * 16; rows_used = 48; TOTC = 8;
        W0h = g_wf16[0][0]; W0l = g_wf16[0][1]; W1h = W0h; W1l = W0l;
    } else if (cta < 64) {
        role = 1; lay = 1; n0 = (cta - 32) * 16; rows_used = 48; TOTC = 16;
        W0h = g_wf16[1][0]; W0l = g_wf16[1][1]; W1h = g_wf16[2][0]; W1l = g_wf16[2][1];
    } else if (cta < 96) {
        role = 2; lay = 2; n0 = (cta - 64) * 16; rows_used = 48; TOTC = 16;
        W0h = g_wf16[3][0]; W0l = g_wf16[3][1]; W1h = g_wf16[4][0]; W1l = g_wf16[4][1];
    } else {
        role = 3; lay = 3; vbase = (cta - 96) * 24; rows_used = 24; TOTC = 8;
        W0h = g_wf16[5][0]; W0l = g_wf16[5][1]; W1h = W0h; W1l = W0l;
    }
    const int choff = (cta * 5) & (TOTC - 1);

    // ---- rowmap ----
    for (int r = tid; r < rows_used; r += NTHR) {
        int grow;
        if (role < 3) {
            int blk = r >> 3, w = blk / 3, gate = blk % 3;
            grow = gate * HH + n0 + w * 8 + (r & 7);
        } else {
            grow = vbase + r;
            if (grow > 64) grow = 0;
        }
        rowmap[r] = grow;
    }
    __syncthreads();

    // ---- register-resident hidden state (this thread's 4 (b,g) elements) ----
    float hreg[4] = {0.f, 0.f, 0.f, 0.f};
    const int b0 = warp8 * 16 + (lane >> 2);
    const int g0 = n0 + wg * 8 + (lane & 3) * 2;

    for (int s = 0; s < TT + 3; ++s) {
        const int rd = (s + 1) & 1, wr = s & 1;

        if (role == 0 && s < TT) {
            const int t = s;
            float acc[1][3][4] = {};
            gemm_run<0, 1>(g_hA[0][rd], g_hA[0][rd], W0h, W0l, W1h, W1l,
                           rows_used, rowmap, sbuf, choff, acc, tid, wg);
            __half* slab = g_hA[0][wr];
            #pragma unroll
            for (int bs = 0; bs < 2; ++bs) {
                const int b = b0 + 8 * bs;
                const int tok = __ldg(x_seq + (long)b * TT + t);
                const float* ig = g_ig0 + (long)tok * 1536;
                float hh[2];
                #pragma unroll
                for (int d = 0; d < 2; ++d) {
                    const int g = g0 + d, idx = bs * 2 + d;
                    float r = sigm(__ldg(ig + g) + acc[0][0][idx]);
                    float z = sigm(__ldg(ig + 512 + g) + acc[0][1][idx]);
                    float n = tanhf(__ldg(ig + 1024 + g)
                                    + r * (acc[0][2][idx] + __ldg(b_n + g)));
                    float h = n + z * (hreg[idx] - n);
                    hreg[idx] = h; hh[d] = h;
                }
                __half2 hv; hv.x = __float2half(hh[0]); hv.y = __float2half(hh[1]);
                *(__half2*)(slab + (long)b * HH + g0) = hv;
            }
        } else if ((role == 1 || role == 2) && s >= lay && s <= TT + lay - 1) {
            float acc[2][3][4] = {};
            gemm_run<0, 2>(g_hA[lay - 1][rd], g_hA[lay][rd], W0h, W0l, W1h, W1l,
                           rows_used, rowmap, sbuf, choff, acc, tid, wg);
            const float* bl = bias + (long)lay * 1536;
            const float* bnl = b_n + (long)lay * 512;
            __half* slab = g_hA[lay][wr];
            #pragma unroll
            for (int bs = 0; bs < 2; ++bs) {
                const int b = b0 + 8 * bs;
                float hh[2];
                #pragma unroll
                for (int d = 0; d < 2; ++d) {
                    const int g = g0 + d, idx = bs * 2 + d;
                    float ir = acc[0][0][idx] + __ldg(bl + g);
                    float iz = acc[0][1][idx] + __ldg(bl + 512 + g);
                    float in_ = acc[0][2][idx] + __ldg(bl + 1024 + g);
                    float r = sigm(ir + acc[1][0][idx]);
                    float z = sigm(iz + acc[1][1][idx]);
                    float n = tanhf(in_ + r * (acc[1][2][idx] + __ldg(bnl + g)));
                    float h = n + z * (hreg[idx] - n);
                    hreg[idx] = h; hh[d] = h;
                }
                __half2 hv; hv.x = __float2half(hh[0]); hv.y = __float2half(hh[1]);
                *(__half2*)(slab + (long)b * HH + g0) = hv;
            }
        } else if (role == 3 && s >= 3) {
            const int t = s - 3;
            float acc[1][3][4] = {};
            if (wg == 0) {
                gemm_run<1, 1>(g_hA[2][rd], g_hA[2][rd], W0h, W0l, W1h, W1l,
                               rows_used, rowmap, sbuf, choff, acc, tid, wg);
                #pragma unroll
                for (int j = 0; j < 2; ++j) {
                    #pragma unroll
                    for (int bs = 0; bs < 2; ++bs) {
                        const int b = b0 + 8 * bs;
                        #pragma unroll
                        for (int d = 0; d < 2; ++d) {
                            int v = vbase + j * 8 + (lane & 3) * 2 + d;
                            if (v < 65)
                                out[((long)b * TT + t) * 65 + v] =
                                    acc[0][j][bs * 2 + d] + __ldg(b_out + v);
                        }
                    }
                }
            } else {
                gemm_run<2, 1>(g_hA[2][rd], g_hA[2][rd], W0h, W0l, W1h, W1l,
                               rows_used, rowmap, sbuf, choff, acc, tid, wg);
                #pragma unroll
                for (int bs = 0; bs < 2; ++bs) {
                    const int b = b0 + 8 * bs;
                    #pragma unroll
                    for (int d = 0; d < 2; ++d) {
                        int v = vbase + 16 + (lane & 3) * 2 + d;
                        if (v < 65)
                            out[((long)b * TT + t) * 65 + v] =
                                acc[0][2][bs * 2 + d] + __ldg(b_out + v);
                    }
                }
            }
        }

        grid_barrier((unsigned)(s + 1), cta, tid);
    }
}

// --------------------------------- launch ------------------------------------
extern "C" void kernel_launch(void* const* d_in, const int* in_sizes, int n_in,
                              void* d_out, int out_size) {
    const int*   x_seq = (const int*)  d_in[0];
    const float* emb   = (const float*)d_in[1];
    const float* w_ih  = (const float*)d_in[2];
    const float* w_hh  = (const float*)d_in[3];
    const float* b     = (const float*)d_in[4];
    const float* b_n   = (const float*)d_in[5];
    const float* w_out = (const float*)d_in[6];
    const float* b_out = (const float*)d_in[7];
    float* out = (float*)d_out;

    cudaFuncSetAttribute(k_main, cudaFuncAttributeMaxDynamicSharedMemorySize, SMEM_BYTES);

    k_zero<<<512, 256>>>();
    k_ig0<<<(65 * 1536 + 255) / 256, 256>>>(emb, w_ih, b);
    k_prepw<<<(int)((6L * 1536 * 512 + 255) / 256), 256>>>(w_ih, w_hh, w_out);
    k_main<<<NCTA, NTHR, SMEM_BYTES>>>(x_seq, b, b_n, b_out, out);
}

// round 10
// speedup vs baseline: 2.1784x; 1.4123x over previous
#include <cuda_runtime.h>
#include <cuda_fp16.h>
#include <cstdint>
#include <math.h>

#define BB 128
#define TT 1024
#define HH 512
#define NCTA 99
#define NTHR 512

// smem: 3 A-buffers (128 rows x 272B) + persistent W (max 48 x 2064B)
#define ABYTES 34816
#define OFF_W  (3 * ABYTES)                // 104448
#define SMEM_BYTES (OFF_W + 48 * 2064)     // 203520

// ------------------------- persistent device state ---------------------------
__device__ float g_ig0[65 * 1536];                        // layer0 igates + bias
__device__ __align__(16) __half g_hA[3][2][BB * HH];      // fp16 h slabs [lay][pp]
__device__ __align__(16) __half g_wf16s[6][1536 * 512];   // fp16 weights [part]
__device__ unsigned g_flags[NCTA];
__device__ unsigned g_gen;

// ------------------------------ helpers --------------------------------------
__device__ __forceinline__ float sigm(float x) { return 1.f / (1.f + __expf(-x)); }
__device__ __forceinline__ uint32_t smem_u32(const void* p) {
    uint32_t a;
    asm("{ .reg .u64 t; cvta.to.shared.u64 t, %1; cvt.u32.u64 %0, t; }" : "=r"(a) : "l"(p));
    return a;
}
__device__ __forceinline__ void ldsm4(uint32_t a, uint32_t& r0, uint32_t& r1,
                                      uint32_t& r2, uint32_t& r3) {
    asm volatile("ldmatrix.sync.aligned.m8n8.x4.shared.b16 {%0,%1,%2,%3}, [%4];"
                 : "=r"(r0), "=r"(r1), "=r"(r2), "=r"(r3) : "r"(a));
}
__device__ __forceinline__ void ldsm2(uint32_t a, uint32_t& r0, uint32_t& r1) {
    asm volatile("ldmatrix.sync.aligned.m8n8.x2.shared.b16 {%0,%1}, [%2];"
                 : "=r"(r0), "=r"(r1) : "r"(a));
}
__device__ __forceinline__ void mma4(float* d, uint32_t a0, uint32_t a1, uint32_t a2,
                                     uint32_t a3, uint32_t b0, uint32_t b1) {
    asm volatile("mma.sync.aligned.m16n8k16.row.col.f32.f16.f16.f32 "
                 "{%0,%1,%2,%3},{%4,%5,%6,%7},{%8,%9},{%0,%1,%2,%3};"
                 : "+f"(d[0]), "+f"(d[1]), "+f"(d[2]), "+f"(d[3])
                 : "r"(a0), "r"(a1), "r"(a2), "r"(a3), "r"(b0), "r"(b1));
}
__device__ __forceinline__ void cp16(uint32_t dst, const void* src) {
    asm volatile("cp.async.cg.shared.global [%0], [%1], 16;" :: "r"(dst), "l"(src));
}
#define CP_COMMIT() asm volatile("cp.async.commit_group;" ::: "memory")
#define CP_WAIT1()  asm volatile("cp.async.wait_group 1;" ::: "memory")
#define CP_WAIT0()  asm volatile("cp.async.wait_group 0;" ::: "memory")

// ------------------------------ prep kernels ---------------------------------
__global__ void k_zero() {
    long i = (long)blockIdx.x * blockDim.x + threadIdx.x;
    __half* ph = &g_hA[0][0][0];
    long nh = 3L * 2 * BB * HH;
    for (long j = i; j < nh; j += (long)gridDim.x * blockDim.x) ph[j] = __float2half(0.f);
    if (i < NCTA) g_flags[i] = 0u;
    if (i == 0) g_gen = 0u;
}

__global__ void k_ig0(const float* __restrict__ emb, const float* __restrict__ w_ih,
                      const float* __restrict__ bias) {
    int idx = blockIdx.x * blockDim.x + threadIdx.x;
    if (idx >= 65 * 1536) return;
    int tok = idx / 1536, j = idx - tok * 1536;
    const float* e = emb + tok * HH;
    const float* w = w_ih + (long)j * HH;
    float acc = bias[j];
    #pragma unroll 8
    for (int k = 0; k < HH; ++k) acc += e[k] * w[k];
    g_ig0[idx] = acc;
}

__global__ void k_prepw(const float* __restrict__ w_ih, const float* __restrict__ w_hh,
                        const float* __restrict__ w_out) {
    long idx = (long)blockIdx.x * 256 + threadIdx.x;     // 6 * 1536 * 512
    if (idx >= 6L * 1536 * 512) return;
    int k = (int)(idx & 511);
    long r = idx >> 9;
    int row = (int)(r % 1536);
    int part = (int)(r / 1536);
    float v = 0.f;
    if (part == 0)      v = w_hh[(long)row * 512 + k];
    else if (part == 1) v = w_ih[(1536L + row) * 512 + k];
    else if (part == 2) v = w_hh[(1536L + row) * 512 + k];
    else if (part == 3) v = w_ih[(2L * 1536 + row) * 512 + k];
    else if (part == 4) v = w_hh[(2L * 1536 + row) * 512 + k];
    else if (row < 65)  v = w_out[(long)row * 512 + k];
    g_wf16s[part][(long)row * 512 + k] = __float2half(v);
}

// ---------------- hierarchical grid barrier (low-contention) -----------------
__device__ __forceinline__ void grid_barrier(unsigned target, int cta, int tid) {
    __syncthreads();
    __threadfence();
    if (tid == 0) *((volatile unsigned*)&g_flags[cta]) = target;
    if (cta == 0) {
        if (tid < NCTA) {
            while (*((volatile unsigned*)&g_flags[tid]) < target) { }
        }
        __syncthreads();
        if (tid == 0) { __threadfence(); *((volatile unsigned*)&g_gen) = target; }
    }
    if (tid == 0) {
        while (*((volatile unsigned*)&g_gen) < target) { }
    }
    __syncthreads();
}

// ------------------------------ GEMM core ------------------------------------
// W persistent in smem (single fp16 plane). A streamed in K=128 chunks,
// 3 buffers, 1 __syncthreads per chunk, staggered chunk order per CTA.
// MODE 0: layer CTA (wg rows wg*24: r/z via x4, n via x2) -> 3 gate tiles
// MODE 1: out CTA wg0 (rows 0-15 via x4) -> tiles 0,1
// MODE 2: out CTA wg1 (rows 16-23 via x2) -> tile 2
template <int MODE, int NPH>
__device__ __forceinline__ void gemm_run(
    const __half* __restrict__ A0, const __half* __restrict__ A1,
    uint32_t wbase, uint32_t pitchWB, uint32_t sbuf, int choff,
    float (&acc)[NPH][3][4], int tid, int wg)
{
    const int lane = tid & 31, warp8 = (tid >> 5) & 7;
    const int lr = lane & 7, gq = lane >> 3;
    const uint32_t aoff = (uint32_t)((warp8 * 16 + lr + (gq & 1) * 8) * 272
                                     + (gq >> 1) * 16);
    const int wrowbase = (MODE == 0) ? wg * 24 : 0;
    const uint32_t w4row = (uint32_t)(wrowbase + lr + (gq & 1) * 8) * pitchWB;
    const uint32_t w2row = (uint32_t)(wrowbase + 16 + lr) * pitchWB;
    const uint32_t k4sub = (uint32_t)((gq >> 1) * 8) * 2;
    const uint32_t k2sub = (uint32_t)(((lane >> 3) & 1) * 8) * 2;
    const int TOT = NPH * 4;

    auto stage = [&](int j) {
        int cg = (j + choff) & (TOT - 1);
        int ph = cg >> 2, kc = cg & 3;
        const __half* a = ph ? A1 : A0;
        const __half* s0 = a + kc * 128;
        uint32_t buf = sbuf + (uint32_t)(j % 3) * ABYTES;
        #pragma unroll
        for (int i = 0; i < 4; ++i) {
            int e = tid + i * NTHR;
            int rr = e >> 4, u = e & 15;
            cp16(buf + (uint32_t)(rr * 272 + u * 16), s0 + (long)rr * HH + u * 8);
        }
        CP_COMMIT();
    };

    stage(0); stage(1);
    #pragma unroll 1
    for (int j = 0; j < TOT; ++j) {
        if (j == TOT - 1) CP_WAIT0(); else CP_WAIT1();
        __syncthreads();
        if (j + 2 < TOT) stage(j + 2);
        const int cg = (j + choff) & (TOT - 1);
        const int ph = cg >> 2;
        const uint32_t kbase = (uint32_t)((ph * 512 + (cg & 3) * 128) * 2);
        const uint32_t buf = sbuf + (uint32_t)(j % 3) * ABYTES;
        #pragma unroll
        for (int ks = 0; ks < 8; ++ks) {
            uint32_t a0, a1, a2, a3;
            ldsm4(buf + aoff + ks * 32, a0, a1, a2, a3);
            const uint32_t kk = kbase + ks * 32;
            if (MODE == 0) {
                uint32_t h0, h1, h2, h3, h4v, h5;
                ldsm4(wbase + w4row + kk + k4sub, h0, h1, h2, h3);
                ldsm2(wbase + w2row + kk + k2sub, h4v, h5);
                mma4(acc[ph][0], a0, a1, a2, a3, h0, h2);
                mma4(acc[ph][1], a0, a1, a2, a3, h1, h3);
                mma4(acc[ph][2], a0, a1, a2, a3, h4v, h5);
            } else if (MODE == 1) {
                uint32_t h0, h1, h2, h3;
                ldsm4(wbase + w4row + kk + k4sub, h0, h1, h2, h3);
                mma4(acc[ph][0], a0, a1, a2, a3, h0, h2);
                mma4(acc[ph][1], a0, a1, a2, a3, h1, h3);
            } else {
                uint32_t h4v, h5;
                ldsm2(wbase + w2row + kk + k2sub, h4v, h5);
                mma4(acc[ph][2], a0, a1, a2, a3, h4v, h5);
            }
        }
    }
    __syncthreads();
}

// ------------------------------- main kernel ---------------------------------
__global__ void __launch_bounds__(NTHR, 1) k_main(
    const int* __restrict__ x_seq,
    const float* __restrict__ bias, const float* __restrict__ b_n,
    const float* __restrict__ b_out, float* __restrict__ out)
{
    extern __shared__ unsigned char smem[];
    const uint32_t sbuf = smem_u32(smem);
    const uint32_t wbase = sbuf + OFF_W;
    const int tid = threadIdx.x;
    const int wg = tid >> 8;
    const int lane = tid & 31, warp8 = (tid >> 5) & 7;
    const int cta = blockIdx.x;

    // ---- role decode ----
    int role, lay = 0, n0 = 0, vbase = 0, rows_used, ktot, TOTC, p0, p1;
    if (cta < 32) {
        role = 0; lay = 0; n0 = cta * 16; rows_used = 48; ktot = 512; TOTC = 4;
        p0 = 0; p1 = 0;
    } else if (cta < 64) {
        role = 1; lay = 1; n0 = (cta - 32) * 16; rows_used = 48; ktot = 1024; TOTC = 8;
        p0 = 1; p1 = 2;
    } else if (cta < 96) {
        role = 2; lay = 2; n0 = (cta - 64) * 16; rows_used = 48; ktot = 1024; TOTC = 8;
        p0 = 3; p1 = 4;
    } else {
        role = 3; lay = 3; vbase = (cta - 96) * 24; rows_used = 24; ktot = 512; TOTC = 4;
        p0 = 5; p1 = 5;
    }
    const int pitchWE = ktot + 8;
    const uint32_t pitchWB = (uint32_t)pitchWE * 2;
    const int choff = (cta * 5) & (TOTC - 1);

    // ---- persistent W load (once) ----
    {
        __half* ws = (__half*)(smem + OFF_W);
        for (int e = tid; e < rows_used * ktot; e += NTHR) {
            int r = e / ktot, k = e - r * ktot;
            int grow;
            if (role < 3) {
                int blk = r >> 3, w = blk / 3, gate = blk % 3;
                grow = gate * HH + n0 + w * 8 + (r & 7);
            } else {
                grow = vbase + r;
                if (grow > 64) grow = 0;
            }
            int part = (k < 512) ? p0 : p1;
            ws[r * pitchWE + k] = g_wf16s[part][(long)grow * 512 + (k & 511)];
        }
    }
    __syncthreads();

    // ---- register-resident hidden state (this thread's 4 (b,g) elements) ----
    float hreg[4] = {0.f, 0.f, 0.f, 0.f};
    const int b0 = warp8 * 16 + (lane >> 2);
    const int g0 = n0 + wg * 8 + (lane & 3) * 2;

    for (int s = 0; s < TT + 3; ++s) {
        const int rd = (s + 1) & 1, wr = s & 1;

        if (role == 0 && s < TT) {
            const int t = s;
            float acc[1][3][4] = {};
            gemm_run<0, 1>(g_hA[0][rd], g_hA[0][rd], wbase, pitchWB, sbuf, choff,
                           acc, tid, wg);
            __half* slab = g_hA[0][wr];
            #pragma unroll
            for (int bs = 0; bs < 2; ++bs) {
                const int b = b0 + 8 * bs;
                const int tok = __ldg(x_seq + (long)b * TT + t);
                const float* ig = g_ig0 + (long)tok * 1536;
                float hh[2];
                #pragma unroll
                for (int d = 0; d < 2; ++d) {
                    const int g = g0 + d, idx = bs * 2 + d;
                    float r = sigm(__ldg(ig + g) + acc[0][0][idx]);
                    float z = sigm(__ldg(ig + 512 + g) + acc[0][1][idx]);
                    float n = tanhf(__ldg(ig + 1024 + g)
                                    + r * (acc[0][2][idx] + __ldg(b_n + g)));
                    float h = n + z * (hreg[idx] - n);
                    hreg[idx] = h; hh[d] = h;
                }
                __half2 hv; hv.x = __float2half(hh[0]); hv.y = __float2half(hh[1]);
                *(__half2*)(slab + (long)b * HH + g0) = hv;
            }
        } else if ((role == 1 || role == 2) && s >= lay && s <= TT + lay - 1) {
            float acc[2][3][4] = {};
            gemm_run<0, 2>(g_hA[lay - 1][rd], g_hA[lay][rd], wbase, pitchWB, sbuf, choff,
                           acc, tid, wg);
            const float* bl = bias + (long)lay * 1536;
            const float* bnl = b_n + (long)lay * 512;
            __half* slab = g_hA[lay][wr];
            #pragma unroll
            for (int bs = 0; bs < 2; ++bs) {
                const int b = b0 + 8 * bs;
                float hh[2];
                #pragma unroll
                for (int d = 0; d < 2; ++d) {
                    const int g = g0 + d, idx = bs * 2 + d;
                    float ir = acc[0][0][idx] + __ldg(bl + g);
                    float iz = acc[0][1][idx] + __ldg(bl + 512 + g);
                    float in_ = acc[0][2][idx] + __ldg(bl + 1024 + g);
                    float r = sigm(ir + acc[1][0][idx]);
                    float z = sigm(iz + acc[1][1][idx]);
                    float n = tanhf(in_ + r * (acc[1][2][idx] + __ldg(bnl + g)));
                    float h = n + z * (hreg[idx] - n);
                    hreg[idx] = h; hh[d] = h;
                }
                __half2 hv; hv.x = __float2half(hh[0]); hv.y = __float2half(hh[1]);
                *(__half2*)(slab + (long)b * HH + g0) = hv;
            }
        } else if (role == 3 && s >= 3) {
            const int t = s - 3;
            float acc[1][3][4] = {};
            if (wg == 0) {
                gemm_run<1, 1>(g_hA[2][rd], g_hA[2][rd], wbase, pitchWB, sbuf, choff,
                               acc, tid, wg);
                #pragma unroll
                for (int j = 0; j < 2; ++j) {
                    #pragma unroll
                    for (int bs = 0; bs < 2; ++bs) {
                        const int b = b0 + 8 * bs;
                        #pragma unroll
                        for (int d = 0; d < 2; ++d) {
                            int v = vbase + j * 8 + (lane & 3) * 2 + d;
                            if (v < 65)
                                out[((long)b * TT + t) * 65 + v] =
                                    acc[0][j][bs * 2 + d] + __ldg(b_out + v);
                        }
                    }
                }
            } else {
                gemm_run<2, 1>(g_hA[2][rd], g_hA[2][rd], wbase, pitchWB, sbuf, choff,
                               acc, tid, wg);
                #pragma unroll
                for (int bs = 0; bs < 2; ++bs) {
                    const int b = b0 + 8 * bs;
                    #pragma unroll
                    for (int d = 0; d < 2; ++d) {
                        int v = vbase + 16 + (lane & 3) * 2 + d;
                        if (v < 65)
                            out[((long)b * TT + t) * 65 + v] =
                                acc[0][2][bs * 2 + d] + __ldg(b_out + v);
                    }
                }
            }
        }

        grid_barrier((unsigned)(s + 1), cta, tid);
    }
}

// --------------------------------- launch ------------------------------------
extern "C" void kernel_launch(void* const* d_in, const int* in_sizes, int n_in,
                              void* d_out, int out_size) {
    const int*   x_seq = (const int*)  d_in[0];
    const float* emb   = (const float*)d_in[1];
    const float* w_ih  = (const float*)d_in[2];
    const float* w_hh  = (const float*)d_in[3];
    const float* b     = (const float*)d_in[4];
    const float* b_n   = (const float*)d_in[5];
    const float* w_out = (const float*)d_in[6];
    const float* b_out = (const float*)d_in[7];
    float* out = (float*)d_out;

    cudaFuncSetAttribute(k_main, cudaFuncAttributeMaxDynamicSharedMemorySize, SMEM_BYTES);

    k_zero<<<512, 256>>>();
    k_ig0<<<(65 * 1536 + 255) / 256, 256>>>(emb, w_ih, b);
    k_prepw<<<(int)((6L * 1536 * 512 + 255) / 256), 256>>>(w_ih, w_hh, w_out);
    k_main<<<NCTA, NTHR, SMEM_BYTES>>>(x_seq, b, b_n, b_out, out);
}

// round 11
// speedup vs baseline: 2.9178x; 1.3394x over previous
#include <cuda_runtime.h>
#include <cuda_fp16.h>
#include <cstdint>
#include <math.h>

#define BB 128
#define TT 1024
#define HH 512
#define NCTA 99
#define NTHR 512
#define RING 4

// smem: 3 A-buffers (128 rows x 272B) + persistent W (max 48 x 2064B)
#define ABYTES 34816
#define OFF_W  (3 * ABYTES)                // 104448
#define SMEM_BYTES (OFF_W + 48 * 2064)     // 203520

// ------------------------- persistent device state ---------------------------
__device__ float g_ig0[65 * 1536];                        // layer0 igates + bias
__device__ __align__(16) __half g_hA[3][RING][BB * HH];   // fp16 h ring [lay][slot]
__device__ __align__(16) __half g_wf16s[6][1536 * 512];   // fp16 weights [part]
__device__ unsigned g_prod[3];   // 32 * steps completed per layer
__device__ unsigned g_cons[3];   // external consumptions of layer l's output

// ------------------------------ helpers --------------------------------------
__device__ __forceinline__ float sigm(float x) { return 1.f / (1.f + __expf(-x)); }
__device__ __forceinline__ uint32_t smem_u32(const void* p) {
    uint32_t a;
    asm("{ .reg .u64 t; cvta.to.shared.u64 t, %1; cvt.u32.u64 %0, t; }" : "=r"(a) : "l"(p));
    return a;
}
__device__ __forceinline__ void ldsm4(uint32_t a, uint32_t& r0, uint32_t& r1,
                                      uint32_t& r2, uint32_t& r3) {
    asm volatile("ldmatrix.sync.aligned.m8n8.x4.shared.b16 {%0,%1,%2,%3}, [%4];"
                 : "=r"(r0), "=r"(r1), "=r"(r2), "=r"(r3) : "r"(a));
}
__device__ __forceinline__ void ldsm2(uint32_t a, uint32_t& r0, uint32_t& r1) {
    asm volatile("ldmatrix.sync.aligned.m8n8.x2.shared.b16 {%0,%1}, [%2];"
                 : "=r"(r0), "=r"(r1) : "r"(a));
}
__device__ __forceinline__ void mma4(float* d, uint32_t a0, uint32_t a1, uint32_t a2,
                                     uint32_t a3, uint32_t b0, uint32_t b1) {
    asm volatile("mma.sync.aligned.m16n8k16.row.col.f32.f16.f16.f32 "
                 "{%0,%1,%2,%3},{%4,%5,%6,%7},{%8,%9},{%0,%1,%2,%3};"
                 : "+f"(d[0]), "+f"(d[1]), "+f"(d[2]), "+f"(d[3])
                 : "r"(a0), "r"(a1), "r"(a2), "r"(a3), "r"(b0), "r"(b1));
}
__device__ __forceinline__ void cp16(uint32_t dst, const void* src) {
    asm volatile("cp.async.cg.shared.global [%0], [%1], 16;" :: "r"(dst), "l"(src));
}
#define CP_COMMIT() asm volatile("cp.async.commit_group;" ::: "memory")
#define CP_WAIT1()  asm volatile("cp.async.wait_group 1;" ::: "memory")
#define CP_WAIT0()  asm volatile("cp.async.wait_group 0;" ::: "memory")

// thread-0 poll until *p >= target, then block-wide release
__device__ __forceinline__ void wait_ge(volatile unsigned* p, unsigned target, int tid) {
    if (tid == 0) {
        while (*p < target) { }
    }
    __syncthreads();
}

// ------------------------------ prep kernels ---------------------------------
__global__ void k_zero() {
    long i = (long)blockIdx.x * blockDim.x + threadIdx.x;
    __half* ph = &g_hA[0][0][0];
    long nh = 3L * RING * BB * HH;
    for (long j = i; j < nh; j += (long)gridDim.x * blockDim.x) ph[j] = __float2half(0.f);
    if (i < 3) { g_prod[i] = 0u; g_cons[i] = 0u; }
}

__global__ void k_ig0(const float* __restrict__ emb, const float* __restrict__ w_ih,
                      const float* __restrict__ bias) {
    int idx = blockIdx.x * blockDim.x + threadIdx.x;
    if (idx >= 65 * 1536) return;
    int tok = idx / 1536, j = idx - tok * 1536;
    const float* e = emb + tok * HH;
    const float* w = w_ih + (long)j * HH;
    float acc = bias[j];
    #pragma unroll 8
    for (int k = 0; k < HH; ++k) acc += e[k] * w[k];
    g_ig0[idx] = acc;
}

__global__ void k_prepw(const float* __restrict__ w_ih, const float* __restrict__ w_hh,
                        const float* __restrict__ w_out) {
    long idx = (long)blockIdx.x * 256 + threadIdx.x;     // 6 * 1536 * 512
    if (idx >= 6L * 1536 * 512) return;
    int k = (int)(idx & 511);
    long r = idx >> 9;
    int row = (int)(r % 1536);
    int part = (int)(r / 1536);
    float v = 0.f;
    if (part == 0)      v = w_hh[(long)row * 512 + k];
    else if (part == 1) v = w_ih[(1536L + row) * 512 + k];
    else if (part == 2) v = w_hh[(1536L + row) * 512 + k];
    else if (part == 3) v = w_ih[(2L * 1536 + row) * 512 + k];
    else if (part == 4) v = w_hh[(2L * 1536 + row) * 512 + k];
    else if (row < 65)  v = w_out[(long)row * 512 + k];
    g_wf16s[part][(long)row * 512 + k] = __float2half(v);
}

// ------------------------------ GEMM core ------------------------------------
// 4-chunk (K=512) GEMM from one A slab. W persistent in smem; kcolB selects the
// W column block (0 = x-part / only part, 1024 bytes = h-part for layers 1/2).
// MODE 0: layer CTA (wg rows wg*24: r/z via x4, n via x2) -> 3 gate tiles
// MODE 1: out CTA wg0 (rows 0-15 via x4) -> tiles 0,1
// MODE 2: out CTA wg1 (rows 16-23 via x2) -> tile 2
template <int MODE>
__device__ __forceinline__ void gemm_run(
    const __half* __restrict__ A,
    uint32_t wbase, uint32_t pitchWB, uint32_t kcolB,
    uint32_t sbuf, int choff, float (&acc)[3][4], int tid, int wg)
{
    const int lane = tid & 31, warp8 = (tid >> 5) & 7;
    const int lr = lane & 7, gq = lane >> 3;
    const uint32_t aoff = (uint32_t)((warp8 * 16 + lr + (gq & 1) * 8) * 272
                                     + (gq >> 1) * 16);
    const int wrowbase = (MODE == 0) ? wg * 24 : 0;
    const uint32_t w4row = (uint32_t)(wrowbase + lr + (gq & 1) * 8) * pitchWB;
    const uint32_t w2row = (uint32_t)(wrowbase + 16 + lr) * pitchWB;
    const uint32_t k4sub = (uint32_t)((gq >> 1) * 8) * 2;
    const uint32_t k2sub = (uint32_t)(((lane >> 3) & 1) * 8) * 2;

    auto stage = [&](int j) {
        int cg = (j + choff) & 3;
        const __half* s0 = A + cg * 128;
        uint32_t buf = sbuf + (uint32_t)(j % 3) * ABYTES;
        #pragma unroll
        for (int i = 0; i < 4; ++i) {
            int e = tid + i * NTHR;
            int rr = e >> 4, u = e & 15;
            cp16(buf + (uint32_t)(rr * 272 + u * 16), s0 + (long)rr * HH + u * 8);
        }
        CP_COMMIT();
    };

    stage(0); stage(1);
    #pragma unroll 1
    for (int j = 0; j < 4; ++j) {
        if (j == 3) CP_WAIT0(); else CP_WAIT1();
        __syncthreads();
        if (j + 2 < 4) stage(j + 2);
        const int cg = (j + choff) & 3;
        const uint32_t kbase = kcolB + (uint32_t)cg * 256;
        const uint32_t buf = sbuf + (uint32_t)(j % 3) * ABYTES;
        #pragma unroll
        for (int ks = 0; ks < 8; ++ks) {
            uint32_t a0, a1, a2, a3;
            ldsm4(buf + aoff + ks * 32, a0, a1, a2, a3);
            const uint32_t kk = kbase + ks * 32;
            if (MODE == 0) {
                uint32_t h0, h1, h2, h3, h4v, h5;
                ldsm4(wbase + w4row + kk + k4sub, h0, h1, h2, h3);
                ldsm2(wbase + w2row + kk + k2sub, h4v, h5);
                mma4(acc[0], a0, a1, a2, a3, h0, h2);
                mma4(acc[1], a0, a1, a2, a3, h1, h3);
                mma4(acc[2], a0, a1, a2, a3, h4v, h5);
            } else if (MODE == 1) {
                uint32_t h0, h1, h2, h3;
                ldsm4(wbase + w4row + kk + k4sub, h0, h1, h2, h3);
                mma4(acc[0], a0, a1, a2, a3, h0, h2);
                mma4(acc[1], a0, a1, a2, a3, h1, h3);
            } else {
                uint32_t h4v, h5;
                ldsm2(wbase + w2row + kk + k2sub, h4v, h5);
                mma4(acc[2], a0, a1, a2, a3, h4v, h5);
            }
        }
    }
    __syncthreads();
}

// ------------------------------- main kernel ---------------------------------
__global__ void __launch_bounds__(NTHR, 1) k_main(
    const int* __restrict__ x_seq,
    const float* __restrict__ bias, const float* __restrict__ b_n,
    const float* __restrict__ b_out, float* __restrict__ out)
{
    extern __shared__ unsigned char smem[];
    const uint32_t sbuf = smem_u32(smem);
    const uint32_t wbase = sbuf + OFF_W;
    const int tid = threadIdx.x;
    const int wg = tid >> 8;
    const int lane = tid & 31, warp8 = (tid >> 5) & 7;
    const int cta = blockIdx.x;

    // ---- role decode: 32 L0 | 32 L1 | 32 L2 | 3 out ----
    int role, lay = 0, n0 = 0, vbase = 0, rows_used, ktot, p0, p1;
    if (cta < 32) {
        role = 0; lay = 0; n0 = cta * 16; rows_used = 48; ktot = 512; p0 = 0; p1 = 0;
    } else if (cta < 64) {
        role = 1; lay = 1; n0 = (cta - 32) * 16; rows_used = 48; ktot = 1024; p0 = 1; p1 = 2;
    } else if (cta < 96) {
        role = 2; lay = 2; n0 = (cta - 64) * 16; rows_used = 48; ktot = 1024; p0 = 3; p1 = 4;
    } else {
        role = 3; lay = 3; vbase = (cta - 96) * 24; rows_used = 24; ktot = 512; p0 = 5; p1 = 5;
    }
    const int pitchWE = ktot + 8;
    const uint32_t pitchWB = (uint32_t)pitchWE * 2;
    const int choff = (cta * 5) & 3;
    const unsigned consC = (lay == 0 || lay == 1) ? 32u : 3u;   // ext consumers of h[lay]

    // ---- persistent W load (once) ----
    {
        __half* ws = (__half*)(smem + OFF_W);
        for (int e = tid; e < rows_used * ktot; e += NTHR) {
            int r = e / ktot, k = e - r * ktot;
            int grow;
            if (role < 3) {
                int blk = r >> 3, w = blk / 3, gate = blk % 3;
                grow = gate * HH + n0 + w * 8 + (r & 7);
            } else {
                grow = vbase + r;
                if (grow > 64) grow = 0;
            }
            int part = (k < 512) ? p0 : p1;
            ws[r * pitchWE + k] = g_wf16s[part][(long)grow * 512 + (k & 511)];
        }
    }
    __syncthreads();

    // ---- register-resident hidden state ----
    float hreg[4] = {0.f, 0.f, 0.f, 0.f};
    const int b0 = warp8 * 16 + (lane >> 2);
    const int g0 = n0 + wg * 8 + (lane & 3) * 2;

    for (int t = 0; t < TT; ++t) {
        const int wrs = t & (RING - 1);           // write slot
        const int rds = (t - 1) & (RING - 1);     // own previous slot

        if (role == 0) {
            // own h[t-1] fully produced by all 32 L0 CTAs
            wait_ge(&g_prod[0], 32u * (unsigned)t, tid);
            float accH[3][4] = {};
            gemm_run<0>(g_hA[0][rds], wbase, pitchWB, 0, sbuf, choff, accH, tid, wg);
            // ring safety: layer1 must have consumed h0[t-4]
            if (t >= RING) wait_ge(&g_cons[0], 32u * (unsigned)(t - 3), tid);
            __half* slab = g_hA[0][wrs];
            #pragma unroll
            for (int bs = 0; bs < 2; ++bs) {
                const int b = b0 + 8 * bs;
                const int tok = __ldg(x_seq + (long)b * TT + t);
                const float* ig = g_ig0 + (long)tok * 1536;
                float hh[2];
                #pragma unroll
                for (int d = 0; d < 2; ++d) {
                    const int g = g0 + d, idx = bs * 2 + d;
                    float r = sigm(__ldg(ig + g) + accH[0][idx]);
                    float z = sigm(__ldg(ig + 512 + g) + accH[1][idx]);
                    float n = tanhf(__ldg(ig + 1024 + g)
                                    + r * (accH[2][idx] + __ldg(b_n + g)));
                    float h = n + z * (hreg[idx] - n);
                    hreg[idx] = h; hh[d] = h;
                }
                __half2 hv; hv.x = __float2half(hh[0]); hv.y = __float2half(hh[1]);
                *(__half2*)(slab + (long)b * HH + g0) = hv;
            }
            __syncthreads();
            __threadfence();
            if (tid == 0) atomicAdd(&g_prod[0], 1u);
        } else if (role == 1 || role == 2) {
            // phase 1 first: own h[t-1] x W_hh (dep: own layer step t-1)
            wait_ge(&g_prod[lay], 32u * (unsigned)t, tid);
            float accH[3][4] = {};
            gemm_run<0>(g_hA[lay][rds], wbase, pitchWB, 1024, sbuf, choff, accH, tid, wg);
            // phase 0: below-layer h[t] x W_ih (dep: layer lay-1 step t)
            wait_ge(&g_prod[lay - 1], 32u * (unsigned)(t + 1), tid);
            float accI[3][4] = {};
            gemm_run<0>(g_hA[lay - 1][wrs], wbase, pitchWB, 0, sbuf, choff, accI, tid, wg);
            if (tid == 0) atomicAdd(&g_cons[lay - 1], 1u);
            // ring safety
            if (t >= RING) wait_ge(&g_cons[lay], consC * (unsigned)(t - 3), tid);
            const float* bl = bias + (long)lay * 1536;
            const float* bnl = b_n + (long)lay * 512;
            __half* slab = g_hA[lay][wrs];
            #pragma unroll
            for (int bs = 0; bs < 2; ++bs) {
                const int b = b0 + 8 * bs;
                float hh[2];
                #pragma unroll
                for (int d = 0; d < 2; ++d) {
                    const int g = g0 + d, idx = bs * 2 + d;
                    float ir = accI[0][idx] + __ldg(bl + g);
                    float iz = accI[1][idx] + __ldg(bl + 512 + g);
                    float in_ = accI[2][idx] + __ldg(bl + 1024 + g);
                    float r = sigm(ir + accH[0][idx]);
                    float z = sigm(iz + accH[1][idx]);
                    float n = tanhf(in_ + r * (accH[2][idx] + __ldg(bnl + g)));
                    float h = n + z * (hreg[idx] - n);
                    hreg[idx] = h; hh[d] = h;
                }
                __half2 hv; hv.x = __float2half(hh[0]); hv.y = __float2half(hh[1]);
                *(__half2*)(slab + (long)b * HH + g0) = hv;
            }
            __syncthreads();
            __threadfence();
            if (tid == 0) atomicAdd(&g_prod[lay], 1u);
        } else {
            // vocab projection: dep on layer2 step t
            wait_ge(&g_prod[2], 32u * (unsigned)(t + 1), tid);
            float acc[3][4] = {};
            if (wg == 0) {
                gemm_run<1>(g_hA[2][wrs], wbase, pitchWB, 0, sbuf, choff, acc, tid, wg);
                #pragma unroll
                for (int j = 0; j < 2; ++j) {
                    #pragma unroll
                    for (int bs = 0; bs < 2; ++bs) {
                        const int b = b0 + 8 * bs;
                        #pragma unroll
                        for (int d = 0; d < 2; ++d) {
                            int v = vbase + j * 8 + (lane & 3) * 2 + d;
                            if (v < 65)
                                out[((long)b * TT + t) * 65 + v] =
                                    acc[j][bs * 2 + d] + __ldg(b_out + v);
                        }
                    }
                }
            } else {
                gemm_run<2>(g_hA[2][wrs], wbase, pitchWB, 0, sbuf, choff, acc, tid, wg);
                #pragma unroll
                for (int bs = 0; bs < 2; ++bs) {
                    const int b = b0 + 8 * bs;
                    #pragma unroll
                    for (int d = 0; d < 2; ++d) {
                        int v = vbase + 16 + (lane & 3) * 2 + d;
                        if (v < 65)
                            out[((long)b * TT + t) * 65 + v] =
                                acc[2][bs * 2 + d] + __ldg(b_out + v);
                    }
                }
            }
            __syncthreads();
            if (tid == 0) atomicAdd(&g_cons[2], 1u);
        }
    }
}

// --------------------------------- launch ------------------------------------
extern "C" void kernel_launch(void* const* d_in, const int* in_sizes, int n_in,
                              void* d_out, int out_size) {
    const int*   x_seq = (const int*)  d_in[0];
    const float* emb   = (const float*)d_in[1];
    const float* w_ih  = (const float*)d_in[2];
    const float* w_hh  = (const float*)d_in[3];
    const float* b     = (const float*)d_in[4];
    const float* b_n   = (const float*)d_in[5];
    const float* w_out = (const float*)d_in[6];
    const float* b_out = (const float*)d_in[7];
    float* out = (float*)d_out;

    cudaFuncSetAttribute(k_main, cudaFuncAttributeMaxDynamicSharedMemorySize, SMEM_BYTES);

    k_zero<<<512, 256>>>();
    k_ig0<<<(65 * 1536 + 255) / 256, 256>>>(emb, w_ih, b);
    k_prepw<<<(int)((6L * 1536 * 512 + 255) / 256), 256>>>(w_ih, w_hh, w_out);
    k_main<<<NCTA, NTHR, SMEM_BYTES>>>(x_seq, b, b_n, b_out, out);
}

// round 12
// speedup vs baseline: 3.1509x; 1.0799x over previous
#include <cuda_runtime.h>
#include <cuda_fp16.h>
#include <cstdint>
#include <math.h>

#define BB 128
#define TT 1024
#define HH 512
#define NCTA 99
#define NTHR 512
#define RING 4

// smem: per-wg 3 A-buffers (128 x 144B) + persistent W + flags
#define ABYTES 18432
#define OFF_W  (2 * 3 * ABYTES)            // 110592
#define OFF_F  (OFF_W + 48 * 2064)         // 209664
#define SMEM_BYTES (OFF_F + 64)            // 209728

// ------------------------- persistent device state ---------------------------
__device__ float g_ig0[65 * 1536];                        // layer0 igates + bias
__device__ __align__(16) __half g_hA[3][RING][BB * HH];   // fp16 h ring [lay][slot]
__device__ __align__(16) __half g_wf16s[6][1536 * 512];   // fp16 weights [part]
__device__ unsigned g_prod[3];   // 32 * steps completed per layer
__device__ unsigned g_cons[3];   // external consumptions of layer l's output

// ------------------------------ helpers --------------------------------------
__device__ __forceinline__ float sigm(float x) { return 1.f / (1.f + __expf(-x)); }
__device__ __forceinline__ uint32_t smem_u32(const void* p) {
    uint32_t a;
    asm("{ .reg .u64 t; cvta.to.shared.u64 t, %1; cvt.u32.u64 %0, t; }" : "=r"(a) : "l"(p));
    return a;
}
__device__ __forceinline__ void ldsm4(uint32_t a, uint32_t& r0, uint32_t& r1,
                                      uint32_t& r2, uint32_t& r3) {
    asm volatile("ldmatrix.sync.aligned.m8n8.x4.shared.b16 {%0,%1,%2,%3}, [%4];"
                 : "=r"(r0), "=r"(r1), "=r"(r2), "=r"(r3) : "r"(a));
}
__device__ __forceinline__ void ldsm2(uint32_t a, uint32_t& r0, uint32_t& r1) {
    asm volatile("ldmatrix.sync.aligned.m8n8.x2.shared.b16 {%0,%1}, [%2];"
                 : "=r"(r0), "=r"(r1) : "r"(a));
}
__device__ __forceinline__ void mma4(float* d, uint32_t a0, uint32_t a1, uint32_t a2,
                                     uint32_t a3, uint32_t b0, uint32_t b1) {
    asm volatile("mma.sync.aligned.m16n8k16.row.col.f32.f16.f16.f32 "
                 "{%0,%1,%2,%3},{%4,%5,%6,%7},{%8,%9},{%0,%1,%2,%3};"
                 : "+f"(d[0]), "+f"(d[1]), "+f"(d[2]), "+f"(d[3])
                 : "r"(a0), "r"(a1), "r"(a2), "r"(a3), "r"(b0), "r"(b1));
}
__device__ __forceinline__ void cp16(uint32_t dst, const void* src) {
    asm volatile("cp.async.cg.shared.global [%0], [%1], 16;" :: "r"(dst), "l"(src));
}
#define CP_COMMIT() asm volatile("cp.async.commit_group;" ::: "memory")
#define CP_WAIT1()  asm volatile("cp.async.wait_group 1;" ::: "memory")
#define CP_WAIT0()  asm volatile("cp.async.wait_group 0;" ::: "memory")
#define WG_BAR(id)  asm volatile("bar.sync %0, 256;" :: "r"(id) : "memory")

// one poller per warpgroup; release via named barrier
__device__ __forceinline__ void wg_wait(volatile unsigned* p, unsigned target,
                                        bool poller, int barid) {
    if (poller) { while (*p < target) { } }
    WG_BAR(barid);
}

// ------------------------------ prep kernels ---------------------------------
__global__ void k_zero() {
    long i = (long)blockIdx.x * blockDim.x + threadIdx.x;
    __half* ph = &g_hA[0][0][0];
    long nh = 3L * RING * BB * HH;
    for (long j = i; j < nh; j += (long)gridDim.x * blockDim.x) ph[j] = __float2half(0.f);
    if (i < 3) { g_prod[i] = 0u; g_cons[i] = 0u; }
}

__global__ void k_ig0(const float* __restrict__ emb, const float* __restrict__ w_ih,
                      const float* __restrict__ bias) {
    int idx = blockIdx.x * blockDim.x + threadIdx.x;
    if (idx >= 65 * 1536) return;
    int tok = idx / 1536, j = idx - tok * 1536;
    const float* e = emb + tok * HH;
    const float* w = w_ih + (long)j * HH;
    float acc = bias[j];
    #pragma unroll 8
    for (int k = 0; k < HH; ++k) acc += e[k] * w[k];
    g_ig0[idx] = acc;
}

__global__ void k_prepw(const float* __restrict__ w_ih, const float* __restrict__ w_hh,
                        const float* __restrict__ w_out) {
    long idx = (long)blockIdx.x * 256 + threadIdx.x;     // 6 * 1536 * 512
    if (idx >= 6L * 1536 * 512) return;
    int k = (int)(idx & 511);
    long r = idx >> 9;
    int row = (int)(r % 1536);
    int part = (int)(r / 1536);
    float v = 0.f;
    if (part == 0)      v = w_hh[(long)row * 512 + k];
    else if (part == 1) v = w_ih[(1536L + row) * 512 + k];
    else if (part == 2) v = w_hh[(1536L + row) * 512 + k];
    else if (part == 3) v = w_ih[(2L * 1536 + row) * 512 + k];
    else if (part == 4) v = w_hh[(2L * 1536 + row) * 512 + k];
    else if (row < 65)  v = w_out[(long)row * 512 + k];
    g_wf16s[part][(long)row * 512 + k] = __float2half(v);
}

// ------------------------------ GEMM core ------------------------------------
// One warpgroup's K=512 GEMM: 8 chunks of 64 cols, private 3-buffer cp.async
// pipeline, per-wg named barrier. W persistent in smem (kcolB selects x/h part).
// MODE 0: 6 tiles rows 0-47 (3x ldsm4)         [L1/L2 split-K wg]
// MODE 1: 3 tiles rows rowbase..+24 (x4 + x2)  [L0 wg]
// MODE 2: 2 tiles rows 0-15 (x4)               [out wg0]
// MODE 3: 1 tile  rows 16-23 (x2)              [out wg1]
template <int MODE>
__device__ __forceinline__ void gemm_wg(
    const __half* __restrict__ A, uint32_t wbase, uint32_t pitchWB, uint32_t kcolB,
    uint32_t abase, int choff, int rowbase, float (&acc)[6][4], int tid, int barid)
{
    const int ltid = tid & 255;
    const int warpw = (tid >> 5) & 7;
    const int lane = tid & 31;
    const int lr = lane & 7, gq = lane >> 3;
    const uint32_t aoff = (uint32_t)((warpw * 16 + lr + (gq & 1) * 8) * 144
                                     + (gq >> 1) * 16);
    const uint32_t wr0 = (uint32_t)(rowbase + lr + (gq & 1) * 8) * pitchWB;
    const uint32_t wr1 = (uint32_t)(rowbase + 16 + lr + (gq & 1) * 8) * pitchWB;
    const uint32_t wr2 = (uint32_t)(rowbase + 32 + lr + (gq & 1) * 8) * pitchWB;
    const uint32_t wx2 = (uint32_t)(rowbase + 16 + lr) * pitchWB;
    const uint32_t k4 = (uint32_t)((gq >> 1) * 16);
    const uint32_t k2 = (uint32_t)(((lane >> 3) & 1) * 16);

    auto stage = [&](int j) {
        int cg = (j + choff) & 7;
        const __half* s = A + cg * 64;
        uint32_t dst = abase + (uint32_t)(j % 3) * ABYTES;
        #pragma unroll
        for (int i = 0; i < 4; ++i) {
            int e = ltid + i * 256;
            int rr = e >> 3, u = e & 7;
            cp16(dst + (uint32_t)(rr * 144 + u * 16), s + (long)rr * HH + u * 8);
        }
        CP_COMMIT();
    };

    stage(0); stage(1);
    #pragma unroll 1
    for (int j = 0; j < 8; ++j) {
        if (j == 7) CP_WAIT0(); else CP_WAIT1();
        WG_BAR(barid);
        if (j + 2 < 8) stage(j + 2);
        const int cg = (j + choff) & 7;
        const uint32_t kb = kcolB + (uint32_t)cg * 128;
        const uint32_t ab = abase + (uint32_t)(j % 3) * ABYTES;
        #pragma unroll
        for (int ks = 0; ks < 4; ++ks) {
            uint32_t a0, a1, a2, a3;
            ldsm4(ab + aoff + ks * 32, a0, a1, a2, a3);
            const uint32_t kk = kb + ks * 32;
            if (MODE == 0) {
                uint32_t b0, b1, b2, b3;
                ldsm4(wbase + wr0 + kk + k4, b0, b1, b2, b3);
                mma4(acc[0], a0, a1, a2, a3, b0, b2);
                mma4(acc[1], a0, a1, a2, a3, b1, b3);
                ldsm4(wbase + wr1 + kk + k4, b0, b1, b2, b3);
                mma4(acc[2], a0, a1, a2, a3, b0, b2);
                mma4(acc[3], a0, a1, a2, a3, b1, b3);
                ldsm4(wbase + wr2 + kk + k4, b0, b1, b2, b3);
                mma4(acc[4], a0, a1, a2, a3, b0, b2);
                mma4(acc[5], a0, a1, a2, a3, b1, b3);
            } else if (MODE == 1) {
                uint32_t b0, b1, b2, b3, c0, c1;
                ldsm4(wbase + wr0 + kk + k4, b0, b1, b2, b3);
                ldsm2(wbase + wx2 + kk + k2, c0, c1);
                mma4(acc[0], a0, a1, a2, a3, b0, b2);
                mma4(acc[1], a0, a1, a2, a3, b1, b3);
                mma4(acc[2], a0, a1, a2, a3, c0, c1);
            } else if (MODE == 2) {
                uint32_t b0, b1, b2, b3;
                ldsm4(wbase + wr0 + kk + k4, b0, b1, b2, b3);
                mma4(acc[0], a0, a1, a2, a3, b0, b2);
                mma4(acc[1], a0, a1, a2, a3, b1, b3);
            } else {
                uint32_t c0, c1;
                ldsm2(wbase + wx2 + kk + k2, c0, c1);
                mma4(acc[2], a0, a1, a2, a3, c0, c1);
            }
        }
    }
    WG_BAR(barid);    // all warps done; buffers reusable (partial overlay safe)
}

// ------------------------------- main kernel ---------------------------------
__global__ void __launch_bounds__(NTHR, 1) k_main(
    const int* __restrict__ x_seq,
    const float* __restrict__ bias, const float* __restrict__ b_n,
    const float* __restrict__ b_out, float* __restrict__ out)
{
    extern __shared__ unsigned char smem[];
    const uint32_t sbuf = smem_u32(smem);
    const uint32_t wbase = sbuf + OFF_W;
    volatile unsigned* pf = (volatile unsigned*)(smem + OFF_F);
    volatile unsigned* cfl = pf + 1;
    float* partial = (float*)smem;                       // overlays wg0's A bufs
    const int tid = threadIdx.x;
    const int wg = tid >> 8;
    const int ltid = tid & 255;
    const int lane = tid & 31, warpw = (tid >> 5) & 7;
    const int cta = blockIdx.x;
    const uint32_t abase = sbuf + (uint32_t)wg * (3 * ABYTES);
    const bool poller = (ltid == 0);
    const int barid = 1 + wg;

    // ---- role decode: 32 L0 | 32 L1 | 32 L2 | 3 out ----
    int role, lay = 0, n0 = 0, vbase = 0, rows_used, ktot, p0, p1;
    if (cta < 32) {
        role = 0; lay = 0; n0 = cta * 16; rows_used = 48; ktot = 512; p0 = 0; p1 = 0;
    } else if (cta < 64) {
        role = 1; lay = 1; n0 = (cta - 32) * 16; rows_used = 48; ktot = 1024; p0 = 1; p1 = 2;
    } else if (cta < 96) {
        role = 2; lay = 2; n0 = (cta - 64) * 16; rows_used = 48; ktot = 1024; p0 = 3; p1 = 4;
    } else {
        role = 3; lay = 3; vbase = (cta - 96) * 24; rows_used = 24; ktot = 512; p0 = 5; p1 = 5;
    }
    const int pitchWE = ktot + 8;
    const uint32_t pitchWB = (uint32_t)pitchWE * 2;
    const int choff = (cta * 5) & 7;
    const unsigned consC = (lay == 2) ? 3u : 32u;

    // ---- persistent W load + flag init ----
    {
        __half* ws = (__half*)(smem + OFF_W);
        for (int e = tid; e < rows_used * ktot; e += NTHR) {
            int r = e / ktot, k = e - r * ktot;
            int grow;
            if (role < 3) {
                int blk = r >> 3, w = blk / 3, gate = blk % 3;
                grow = gate * HH + n0 + w * 8 + (r & 7);
            } else {
                grow = vbase + r;
                if (grow > 64) grow = 0;
            }
            int part = (k < 512) ? p0 : p1;
            ws[r * pitchWE + k] = g_wf16s[part][(long)grow * 512 + (k & 511)];
        }
    }
    if (tid == 0) { *pf = 0u; *cfl = 0u; }
    __syncthreads();

    const int b0 = warpw * 16 + (lane >> 2);

    if (role == 0) {
        // ---------------- layer 0: both wgs N-split, identical schedule -------
        float hreg[4] = {0.f, 0.f, 0.f, 0.f};
        const int g0 = n0 + wg * 8 + (lane & 3) * 2;
        for (int t = 0; t < TT; ++t) {
            wg_wait(&g_prod[0], 32u * (unsigned)t, poller, barid);
            float acc[6][4] = {};
            gemm_wg<1>(g_hA[0][(t - 1) & 3], wbase, pitchWB, 0, abase, choff,
                       wg * 24, acc, tid, barid);
            if (t >= RING) wg_wait(&g_cons[0], 32u * (unsigned)(t - 3), poller, barid);
            __half* slab = g_hA[0][t & 3];
            #pragma unroll
            for (int bs = 0; bs < 2; ++bs) {
                const int b = b0 + 8 * bs;
                const int tok = __ldg(x_seq + (long)b * TT + t);
                const float* ig = g_ig0 + (long)tok * 1536;
                float hh[2];
                #pragma unroll
                for (int d = 0; d < 2; ++d) {
                    const int g = g0 + d, idx = bs * 2 + d;
                    float r = sigm(__ldg(ig + g) + acc[0][idx]);
                    float z = sigm(__ldg(ig + 512 + g) + acc[1][idx]);
                    float n = tanhf(__ldg(ig + 1024 + g)
                                    + r * (acc[2][idx] + __ldg(b_n + g)));
                    float h = n + z * (hreg[idx] - n);
                    hreg[idx] = h; hh[d] = h;
                }
                __half2 hv; hv.x = __float2half(hh[0]); hv.y = __float2half(hh[1]);
                *(__half2*)(slab + (long)b * HH + g0) = hv;
            }
            __threadfence();
            __syncthreads();
            if (tid == 0) atomicAdd(&g_prod[0], 1u);
        }
    } else if (role == 1 || role == 2) {
        if (wg == 0) {
            // ------------ x-part producer warpgroup --------------------------
            for (int t = 0; t < TT; ++t) {
                if (t >= 1) wg_wait(pf - 1 + 1 == pf ? cfl : cfl, (unsigned)t, poller, 1);
                wg_wait(&g_prod[lay - 1], 32u * (unsigned)(t + 1), poller, 1);
                float acc[6][4] = {};
                gemm_wg<0>(g_hA[lay - 1][t & 3], wbase, pitchWB, 0, abase, choff,
                           0, acc, tid, 1);
                if (tid == 0) atomicAdd(&g_cons[lay - 1], 1u);
                // publish partials into (now idle) own A-buffer region
                #pragma unroll
                for (int i = 0; i < 6; ++i)
                    *(float4*)(partial + ltid * 24 + i * 4) =
                        make_float4(acc[i][0], acc[i][1], acc[i][2], acc[i][3]);
                WG_BAR(1);
                if (tid == 0) *pf = (unsigned)(t + 1);
            }
        } else {
            // ------------ h-part + epilogue warpgroup ------------------------
            float hreg[8] = {0.f, 0.f, 0.f, 0.f, 0.f, 0.f, 0.f, 0.f};
            const float* bl = bias + (long)lay * 1536;
            const float* bnl = b_n + (long)lay * 512;
            for (int t = 0; t < TT; ++t) {
                wg_wait(&g_prod[lay], 32u * (unsigned)t, poller, 2);
                float accH[6][4] = {};
                gemm_wg<0>(g_hA[lay][(t - 1) & 3], wbase, pitchWB, 1024, abase, choff,
                           0, accH, tid, 2);
                wg_wait(pf, (unsigned)(t + 1), poller, 2);
                if (t >= RING) wg_wait(&g_cons[lay], consC * (unsigned)(t - 3), poller, 2);
                __half* slab = g_hA[lay][t & 3];
                const float* myp = partial + ltid * 24;
                #pragma unroll
                for (int cg = 0; cg < 2; ++cg) {
                    const int gb = n0 + cg * 8 + (lane & 3) * 2;
                    #pragma unroll
                    for (int bs = 0; bs < 2; ++bs) {
                        const int b = b0 + 8 * bs;
                        float hh[2];
                        #pragma unroll
                        for (int d = 0; d < 2; ++d) {
                            const int g = gb + d, idx = bs * 2 + d;
                            float ir = myp[(cg * 3 + 0) * 4 + idx] + __ldg(bl + g);
                            float iz = myp[(cg * 3 + 1) * 4 + idx] + __ldg(bl + 512 + g);
                            float in_ = myp[(cg * 3 + 2) * 4 + idx] + __ldg(bl + 1024 + g);
                            float r = sigm(ir + accH[cg * 3 + 0][idx]);
                            float z = sigm(iz + accH[cg * 3 + 1][idx]);
                            float n = tanhf(in_ + r * (accH[cg * 3 + 2][idx] + __ldg(bnl + g)));
                            float h = n + z * (hreg[cg * 4 + idx] - n);
                            hreg[cg * 4 + idx] = h; hh[d] = h;
                        }
                        __half2 hv; hv.x = __float2half(hh[0]); hv.y = __float2half(hh[1]);
                        *(__half2*)(slab + (long)b * HH + gb) = hv;
                    }
                }
                __threadfence();
                WG_BAR(2);
                if (ltid == 0) {
                    *cfl = (unsigned)(t + 1);        // partials consumed
                    atomicAdd(&g_prod[lay], 1u);     // step t published
                }
            }
        }
    } else {
        // ---------------- vocab projection ------------------------------------
        for (int t = 0; t < TT; ++t) {
            wg_wait(&g_prod[2], 32u * (unsigned)(t + 1), poller, barid);
            float acc[6][4] = {};
            if (wg == 0) {
                gemm_wg<2>(g_hA[2][t & 3], wbase, pitchWB, 0, abase, choff,
                           0, acc, tid, 1);
                #pragma unroll
                for (int j = 0; j < 2; ++j) {
                    #pragma unroll
                    for (int bs = 0; bs < 2; ++bs) {
                        const int b = b0 + 8 * bs;
                        #pragma unroll
                        for (int d = 0; d < 2; ++d) {
                            int v = vbase + j * 8 + (lane & 3) * 2 + d;
                            if (v < 65)
                                out[((long)b * TT + t) * 65 + v] =
                                    acc[j][bs * 2 + d] + __ldg(b_out + v);
                        }
                    }
                }
            } else {
                gemm_wg<3>(g_hA[2][t & 3], wbase, pitchWB, 0, abase, choff,
                           0, acc, tid, 2);
                #pragma unroll
                for (int bs = 0; bs < 2; ++bs) {
                    const int b = b0 + 8 * bs;
                    #pragma unroll
                    for (int d = 0; d < 2; ++d) {
                        int v = vbase + 16 + (lane & 3) * 2 + d;
                        if (v < 65)
                            out[((long)b * TT + t) * 65 + v] =
                                acc[2][bs * 2 + d] + __ldg(b_out + v);
                    }
                }
            }
            __syncthreads();
            if (tid == 0) atomicAdd(&g_cons[2], 1u);
        }
    }
}

// --------------------------------- launch ------------------------------------
extern "C" void kernel_launch(void* const* d_in, const int* in_sizes, int n_in,
                              void* d_out, int out_size) {
    const int*   x_seq = (const int*)  d_in[0];
    const float* emb   = (const float*)d_in[1];
    const float* w_ih  = (const float*)d_in[2];
    const float* w_hh  = (const float*)d_in[3];
    const float* b     = (const float*)d_in[4];
    const float* b_n   = (const float*)d_in[5];
    const float* w_out = (const float*)d_in[6];
    const float* b_out = (const float*)d_in[7];
    float* out = (float*)d_out;

    cudaFuncSetAttribute(k_main, cudaFuncAttributeMaxDynamicSharedMemorySize, SMEM_BYTES);

    k_zero<<<512, 256>>>();
    k_ig0<<<(65 * 1536 + 255) / 256, 256>>>(emb, w_ih, b);
    k_prepw<<<(int)((6L * 1536 * 512 + 255) / 256), 256>>>(w_ih, w_hh, w_out);
    k_main<<<NCTA, NTHR, SMEM_BYTES>>>(x_seq, b, b_n, b_out, out);
}